// round 1
// baseline (speedup 1.0000x reference)
#include <cuda_runtime.h>
#include <cuda_bf16.h>
#include <cstdint>

// ---------------------------------------------------------------------------
// EfficientAdditiveAttention fused pipeline (round 0: correctness + tf32 mma)
//
// Shapes: B=16, N=4096, D_IN=512, H=512, T=256, M = B*N = 65536
//
// Math (after algebraic folding):
//   q = x@Wq + bq ; k = x@Wk + bk
//   qw_n = (q_n/max(||q_n||,EPS)) . w_g ; kn_n = k_n/max(||k_n||,EPS)
//   S_b = sum_n qw^2 ; Gacc_b = sum_n qw*q_n
//   G_b = SCALE*Gacc_b / max(SCALE*sqrt(S_b), EPS)      (SCALE cancels unless eps)
//   out = q@Wf + (G ⊙ kn)@(Wp@Wf) + (bp@Wf + bf)
// ---------------------------------------------------------------------------

#define BATCH   16
#define SEQ     4096
#define DIN     512
#define HDIM    512
#define TDIM    256
#define MTOT    (BATCH * SEQ)          // 65536
#define EPS_F   1e-12f
#define SCALE_F 0.044194173824159216f  // 512^-0.5

// Scratch (device globals; no runtime allocation)
__device__ float g_Q[(size_t)MTOT * HDIM];      // q (raw, fp32)
__device__ float g_K[(size_t)MTOT * HDIM];      // k, overwritten with kn
__device__ float g_Wpf[HDIM * TDIM];            // Wp @ Wf
__device__ float g_cpf[TDIM];                   // bp @ Wf + bf
__device__ float g_Gacc[BATCH * HDIM];
__device__ float g_S[BATCH];
__device__ float g_G[BATCH * HDIM];

// ---------------------------------------------------------------------------
// helpers
// ---------------------------------------------------------------------------
__device__ __forceinline__ uint32_t f2tf32(float f) {
    uint32_t u;
    asm("cvt.rna.tf32.f32 %0, %1;" : "=r"(u) : "f"(f));
    return u;
}

__device__ __forceinline__ void mma_tf32(float c[4], const uint32_t a[4], const uint32_t b[2]) {
    asm volatile(
        "mma.sync.aligned.m16n8k8.row.col.f32.tf32.tf32.f32 "
        "{%0,%1,%2,%3}, {%4,%5,%6,%7}, {%8,%9}, {%0,%1,%2,%3};\n"
        : "+f"(c[0]), "+f"(c[1]), "+f"(c[2]), "+f"(c[3])
        : "r"(a[0]), "r"(a[1]), "r"(a[2]), "r"(a[3]), "r"(b[0]), "r"(b[1]));
}

// ---------------------------------------------------------------------------
// Kernel: zero per-batch stats
// ---------------------------------------------------------------------------
__global__ void zero_stats_kernel() {
    int i = blockIdx.x * blockDim.x + threadIdx.x;
    if (i < BATCH * HDIM) g_Gacc[i] = 0.0f;
    if (i < BATCH) g_S[i] = 0.0f;
}

// ---------------------------------------------------------------------------
// Kernel: weight folding   Wpf = Wp@Wf ; cpf = bp@Wf + bf
// blocks 0..31: 16 rows of Wpf each ; block 32: cpf
// ---------------------------------------------------------------------------
__global__ void prep_kernel(const float* __restrict__ Wp, const float* __restrict__ Wf,
                            const float* __restrict__ bp, const float* __restrict__ bf) {
    int j = threadIdx.x;  // 0..255 (column of Wf/Wpf)
    if (blockIdx.x < 32) {
        __shared__ float Wp_s[16][512];
        int i0 = blockIdx.x * 16;
        for (int i = threadIdx.x; i < 16 * 512; i += 256)
            Wp_s[i >> 9][i & 511] = Wp[(size_t)(i0 + (i >> 9)) * 512 + (i & 511)];
        __syncthreads();
        float acc[16];
#pragma unroll
        for (int i = 0; i < 16; ++i) acc[i] = 0.0f;
        for (int k = 0; k < 512; ++k) {
            float wf = Wf[(size_t)k * TDIM + j];
#pragma unroll
            for (int i = 0; i < 16; ++i) acc[i] += Wp_s[i][k] * wf;
        }
#pragma unroll
        for (int i = 0; i < 16; ++i) g_Wpf[(size_t)(i0 + i) * TDIM + j] = acc[i];
    } else {
        __shared__ float bp_s[512];
        for (int i = threadIdx.x; i < 512; i += 256) bp_s[i] = bp[i];
        __syncthreads();
        float a = bf[j];
        for (int k = 0; k < 512; ++k) a += bp_s[k] * Wf[(size_t)k * TDIM + j];
        g_cpf[j] = a;
    }
}

// ---------------------------------------------------------------------------
// Kernel: C = A @ W + bias  (tf32 mma),  A:[M,512] f32 rm, W:[512,Nn] f32 rm
// BM=128 BN=128 BK=32, 256 threads (warp grid 2m x 4n, warp tile 64x32)
// which==0 -> write g_Q, which==1 -> write g_K
// ---------------------------------------------------------------------------
__global__ __launch_bounds__(256, 2)
void gemm_qk_kernel(const float* __restrict__ A, const float* __restrict__ W,
                    const float* __restrict__ bias, int Nn, int which) {
    constexpr int K = 512;
    const int r0 = blockIdx.y * 128;
    const int n0 = blockIdx.x * 128;
    __shared__ uint32_t As[128][36];
    __shared__ uint32_t Ws[32][136];
    const int tid = threadIdx.x;
    const int warp = tid >> 5, lane = tid & 31;
    const int wm = warp >> 2, wn = warp & 3;     // 2 x 4
    const int g = lane >> 2, tg = lane & 3;

    float acc[4][4][4];
#pragma unroll
    for (int a = 0; a < 4; ++a)
#pragma unroll
        for (int b = 0; b < 4; ++b)
#pragma unroll
            for (int c = 0; c < 4; ++c) acc[a][b][c] = 0.0f;

    for (int k0 = 0; k0 < K; k0 += 32) {
#pragma unroll
        for (int it = 0; it < 4; ++it) {                 // A tile 128x32
            int i = tid + it * 256;
            int row = i >> 3, c4 = (i & 7) * 4;
            float4 v = *reinterpret_cast<const float4*>(&A[(size_t)(r0 + row) * K + k0 + c4]);
            As[row][c4 + 0] = f2tf32(v.x);
            As[row][c4 + 1] = f2tf32(v.y);
            As[row][c4 + 2] = f2tf32(v.z);
            As[row][c4 + 3] = f2tf32(v.w);
        }
#pragma unroll
        for (int it = 0; it < 4; ++it) {                 // W tile 32x128
            int i = tid + it * 256;
            int kr = i >> 5, c4 = (i & 31) * 4;
            float4 v = *reinterpret_cast<const float4*>(&W[(size_t)(k0 + kr) * Nn + n0 + c4]);
            Ws[kr][c4 + 0] = f2tf32(v.x);
            Ws[kr][c4 + 1] = f2tf32(v.y);
            Ws[kr][c4 + 2] = f2tf32(v.z);
            Ws[kr][c4 + 3] = f2tf32(v.w);
        }
        __syncthreads();
#pragma unroll
        for (int kk = 0; kk < 4; ++kk) {
            uint32_t af[4][4], bw[4][2];
#pragma unroll
            for (int mf = 0; mf < 4; ++mf) {
                int br = wm * 64 + mf * 16;
                af[mf][0] = As[br + g][kk * 8 + tg];
                af[mf][1] = As[br + g + 8][kk * 8 + tg];
                af[mf][2] = As[br + g][kk * 8 + tg + 4];
                af[mf][3] = As[br + g + 8][kk * 8 + tg + 4];
            }
#pragma unroll
            for (int nf = 0; nf < 4; ++nf) {
                int bc = wn * 32 + nf * 8;
                bw[nf][0] = Ws[kk * 8 + tg][bc + g];
                bw[nf][1] = Ws[kk * 8 + tg + 4][bc + g];
            }
#pragma unroll
            for (int mf = 0; mf < 4; ++mf)
#pragma unroll
                for (int nf = 0; nf < 4; ++nf) mma_tf32(acc[mf][nf], af[mf], bw[nf]);
        }
        __syncthreads();
    }

    float* C = which ? g_K : g_Q;
#pragma unroll
    for (int mf = 0; mf < 4; ++mf) {
#pragma unroll
        for (int nf = 0; nf < 4; ++nf) {
            int row = r0 + wm * 64 + mf * 16 + g;
            int col = n0 + wn * 32 + nf * 8 + tg * 2;
            float b0v = bias[col], b1v = bias[col + 1];
            C[(size_t)row * Nn + col]           = acc[mf][nf][0] + b0v;
            C[(size_t)row * Nn + col + 1]       = acc[mf][nf][1] + b1v;
            C[(size_t)(row + 8) * Nn + col]     = acc[mf][nf][2] + b0v;
            C[(size_t)(row + 8) * Nn + col + 1] = acc[mf][nf][3] + b1v;
        }
    }
}

// ---------------------------------------------------------------------------
// Kernel: rowwise norms + qw + kn (in place) + per-batch reductions
// 512 blocks x 256 threads; each block = 128 rows of one batch
// ---------------------------------------------------------------------------
__global__ void rowwise_kernel(const float* __restrict__ wg) {
    __shared__ float wg_s[512];
    __shared__ float Gs[8][512];
    __shared__ float Sq[8];
    const int tid = threadIdx.x, warp = tid >> 5, lane = tid & 31;
    const int r0 = blockIdx.x * 128;
    const int b = r0 >> 12;

    for (int i = tid; i < 512; i += 256) wg_s[i] = wg[i];
    for (int i = tid; i < 8 * 512; i += 256) (&Gs[0][0])[i] = 0.0f;
    __syncthreads();

    float qw2 = 0.0f;
    for (int rt = 0; rt < 16; ++rt) {
        int r = r0 + rt * 8 + warp;
        const float* qr = g_Q + (size_t)r * HDIM;
        float* kr = g_K + (size_t)r * HDIM;
        float q[16], k[16];
        float sq = 0.0f, sg = 0.0f, sk = 0.0f;
#pragma unroll
        for (int t = 0; t < 16; ++t) {
            int j = lane + 32 * t;
            q[t] = qr[j];
            k[t] = kr[j];
            sq += q[t] * q[t];
            sg += q[t] * wg_s[j];
            sk += k[t] * k[t];
        }
#pragma unroll
        for (int o = 16; o; o >>= 1) {
            sq += __shfl_xor_sync(0xffffffffu, sq, o);
            sg += __shfl_xor_sync(0xffffffffu, sg, o);
            sk += __shfl_xor_sync(0xffffffffu, sk, o);
        }
        float dq = fmaxf(sqrtf(sq), EPS_F);
        float dk = fmaxf(sqrtf(sk), EPS_F);
        float qw = sg / dq;
        float rk = 1.0f / dk;
        qw2 += qw * qw;
#pragma unroll
        for (int t = 0; t < 16; ++t) {
            int j = lane + 32 * t;
            kr[j] = k[t] * rk;               // kn in place
            Gs[warp][j] += qw * q[t];        // weighted pool partial
        }
    }
    if (lane == 0) Sq[warp] = qw2;
    __syncthreads();

    for (int j = tid; j < 512; j += 256) {
        float s = 0.0f;
#pragma unroll
        for (int w = 0; w < 8; ++w) s += Gs[w][j];
        atomicAdd(&g_Gacc[b * HDIM + j], s);
    }
    if (tid == 0) {
        float s = 0.0f;
#pragma unroll
        for (int w = 0; w < 8; ++w) s += Sq[w];
        atomicAdd(&g_S[b], s);
    }
}

// ---------------------------------------------------------------------------
// Kernel: finalize G[b] = SCALE*Gacc[b] / max(SCALE*sqrt(S_b), EPS)
// ---------------------------------------------------------------------------
__global__ void finalize_g_kernel() {
    int b = blockIdx.x, j = threadIdx.x;
    float denom = fmaxf(SCALE_F * sqrtf(g_S[b]), EPS_F);
    g_G[b * HDIM + j] = SCALE_F * g_Gacc[b * HDIM + j] / denom;
}

// ---------------------------------------------------------------------------
// Kernel: out = Q@Wf + (G ⊙ KN)@Wpf + cpf      [M x 256]
// ---------------------------------------------------------------------------
__global__ __launch_bounds__(256, 2)
void gemm_final_kernel(const float* __restrict__ Wf, float* __restrict__ out) {
    constexpr int Nn = TDIM;
    constexpr int K = 512;
    const int r0 = blockIdx.y * 128;
    const int n0 = blockIdx.x * 128;
    const int b = r0 >> 12;
    const float* Gb = g_G + b * HDIM;
    __shared__ uint32_t As[128][36];
    __shared__ uint32_t Ws[32][136];
    const int tid = threadIdx.x;
    const int warp = tid >> 5, lane = tid & 31;
    const int wm = warp >> 2, wn = warp & 3;
    const int g = lane >> 2, tg = lane & 3;

    float acc[4][4][4];
#pragma unroll
    for (int a = 0; a < 4; ++a)
#pragma unroll
        for (int bb = 0; bb < 4; ++bb)
#pragma unroll
            for (int c = 0; c < 4; ++c) acc[a][bb][c] = 0.0f;

    for (int p = 0; p < 2; ++p) {
        const float* Ap = p ? g_K : g_Q;
        const float* Wp2 = p ? g_Wpf : Wf;
        for (int k0 = 0; k0 < K; k0 += 32) {
#pragma unroll
            for (int it = 0; it < 4; ++it) {
                int i = tid + it * 256;
                int row = i >> 3, c4 = (i & 7) * 4;
                float4 v = *reinterpret_cast<const float4*>(&Ap[(size_t)(r0 + row) * K + k0 + c4]);
                if (p) {
                    v.x *= Gb[k0 + c4 + 0];
                    v.y *= Gb[k0 + c4 + 1];
                    v.z *= Gb[k0 + c4 + 2];
                    v.w *= Gb[k0 + c4 + 3];
                }
                As[row][c4 + 0] = f2tf32(v.x);
                As[row][c4 + 1] = f2tf32(v.y);
                As[row][c4 + 2] = f2tf32(v.z);
                As[row][c4 + 3] = f2tf32(v.w);
            }
#pragma unroll
            for (int it = 0; it < 4; ++it) {
                int i = tid + it * 256;
                int kr = i >> 5, c4 = (i & 31) * 4;
                float4 v = *reinterpret_cast<const float4*>(&Wp2[(size_t)(k0 + kr) * Nn + n0 + c4]);
                Ws[kr][c4 + 0] = f2tf32(v.x);
                Ws[kr][c4 + 1] = f2tf32(v.y);
                Ws[kr][c4 + 2] = f2tf32(v.z);
                Ws[kr][c4 + 3] = f2tf32(v.w);
            }
            __syncthreads();
#pragma unroll
            for (int kk = 0; kk < 4; ++kk) {
                uint32_t af[4][4], bw[4][2];
#pragma unroll
                for (int mf = 0; mf < 4; ++mf) {
                    int br = wm * 64 + mf * 16;
                    af[mf][0] = As[br + g][kk * 8 + tg];
                    af[mf][1] = As[br + g + 8][kk * 8 + tg];
                    af[mf][2] = As[br + g][kk * 8 + tg + 4];
                    af[mf][3] = As[br + g + 8][kk * 8 + tg + 4];
                }
#pragma unroll
                for (int nf = 0; nf < 4; ++nf) {
                    int bc = wn * 32 + nf * 8;
                    bw[nf][0] = Ws[kk * 8 + tg][bc + g];
                    bw[nf][1] = Ws[kk * 8 + tg + 4][bc + g];
                }
#pragma unroll
                for (int mf = 0; mf < 4; ++mf)
#pragma unroll
                    for (int nf = 0; nf < 4; ++nf) mma_tf32(acc[mf][nf], af[mf], bw[nf]);
            }
            __syncthreads();
        }
    }

#pragma unroll
    for (int mf = 0; mf < 4; ++mf) {
#pragma unroll
        for (int nf = 0; nf < 4; ++nf) {
            int row = r0 + wm * 64 + mf * 16 + g;
            int col = n0 + wn * 32 + nf * 8 + tg * 2;
            float b0v = g_cpf[col], b1v = g_cpf[col + 1];
            out[(size_t)row * Nn + col]           = acc[mf][nf][0] + b0v;
            out[(size_t)row * Nn + col + 1]       = acc[mf][nf][1] + b1v;
            out[(size_t)(row + 8) * Nn + col]     = acc[mf][nf][2] + b0v;
            out[(size_t)(row + 8) * Nn + col + 1] = acc[mf][nf][3] + b1v;
        }
    }
}

// ---------------------------------------------------------------------------
extern "C" void kernel_launch(void* const* d_in, const int* in_sizes, int n_in,
                              void* d_out, int out_size) {
    const float* x  = (const float*)d_in[0];
    const float* Wq = (const float*)d_in[1];
    const float* bq = (const float*)d_in[2];
    const float* Wk = (const float*)d_in[3];
    const float* bk = (const float*)d_in[4];
    const float* wg = (const float*)d_in[5];
    const float* Wp = (const float*)d_in[6];
    const float* bp = (const float*)d_in[7];
    const float* Wf = (const float*)d_in[8];
    const float* bf = (const float*)d_in[9];
    float* out = (float*)d_out;

    zero_stats_kernel<<<32, 256>>>();
    prep_kernel<<<33, 256>>>(Wp, Wf, bp, bf);
    gemm_qk_kernel<<<dim3(4, 512), 256>>>(x, Wq, bq, HDIM, 0);
    gemm_qk_kernel<<<dim3(4, 512), 256>>>(x, Wk, bk, HDIM, 1);
    rowwise_kernel<<<512, 256>>>(wg);
    finalize_g_kernel<<<16, 512>>>();
    gemm_final_kernel<<<dim3(2, 512), 256>>>(Wf, out);
}

// round 3
// speedup vs baseline: 1.1618x; 1.1618x over previous
#include <cuda_runtime.h>
#include <cstdint>

// ---------------------------------------------------------------------------
// EfficientAdditiveAttention — round 2: legacy tf32 mma (sm_100-safe) +
// cp.async 3-stage pipelined GEMMs + fused Q/K GEMM + per-batch folded weights.
//
// B=16, N=4096, D=H=512, T=256, M=65536
//   q = x@Wq + bq ; k = x@Wk + bk
//   qw = (q/||q||).w_g ; kn = k/||k||
//   S_b = sum qw^2 ; Gacc_b = sum qw*q ; G_b = SCALE*Gacc/max(SCALE*sqrt(S),EPS)
//   out = q@Wf + kn@(diag(G_b)·Wp@Wf) + (bp@Wf + bf)
// ---------------------------------------------------------------------------

#define BATCH   16
#define SEQ     4096
#define HDIM    512
#define TDIM    256
#define MTOT    (BATCH * SEQ)
#define EPS_F   1e-12f
#define SCALE_F 0.044194173824159216f

// ---------------- scratch (device globals; no runtime alloc) ---------------
__device__ float g_Q[(size_t)MTOT * HDIM];              // q (raw fp32)
__device__ float g_K[(size_t)MTOT * HDIM];              // k -> kn in place
__device__ float g_Wpf[HDIM * TDIM];                    // Wp@Wf
__device__ float g_Wpfb[(size_t)BATCH * HDIM * TDIM];   // diag(G_b)·Wpf, per batch
__device__ float g_cpf[TDIM];                           // bp@Wf + bf
__device__ float g_Gacc[BATCH * HDIM];
__device__ float g_S[BATCH];
__device__ float g_G[BATCH * HDIM];

// ---------------------------- helpers --------------------------------------
__device__ __forceinline__ uint32_t f2tf32(float f) {
    uint32_t u;
    asm("cvt.rna.tf32.f32 %0, %1;" : "=r"(u) : "f"(f));
    return u;
}

__device__ __forceinline__ void mma_tf32(float c[4], const uint32_t a[4], const uint32_t b[2]) {
    asm volatile(
        "mma.sync.aligned.m16n8k8.row.col.f32.tf32.tf32.f32 "
        "{%0,%1,%2,%3}, {%4,%5,%6,%7}, {%8,%9}, {%0,%1,%2,%3};\n"
        : "+f"(c[0]), "+f"(c[1]), "+f"(c[2]), "+f"(c[3])
        : "r"(a[0]), "r"(a[1]), "r"(a[2]), "r"(a[3]), "r"(b[0]), "r"(b[1]));
}

__device__ __forceinline__ uint32_t smem_u32(const void* p) {
    uint32_t a;
    asm("{ .reg .u64 t; cvta.to.shared.u64 t, %1; cvt.u32.u64 %0, t; }" : "=r"(a) : "l"(p));
    return a;
}

#define CP_ASYNC16(dst, src) \
    asm volatile("cp.async.cg.shared.global [%0], [%1], 16;" :: "r"(dst), "l"(src) : "memory")
#define CP_COMMIT() asm volatile("cp.async.commit_group;" ::: "memory")
#define CP_WAIT2()  asm volatile("cp.async.wait_group 2;" ::: "memory")

// smem stage geometry: A tile 128x32 fp32 padded to [128][36]; W tile 32x128 padded [32][136]
#define A_PAD 36
#define W_PAD 136
#define A_BYTES (128 * A_PAD * 4)          // 18432
#define STAGE_BYTES (A_BYTES + 32 * W_PAD * 4)  // 18432 + 17408 = 35840
#define NSTG 3
#define SMEM_DYN (NSTG * STAGE_BYTES)      // 107520

// issue cp.async for one (A 128x32, W 32x128) chunk into stage base
__device__ __forceinline__ void load_tile(uint32_t stA, const float* __restrict__ A,
                                          const float* __restrict__ W,
                                          int r0, int n0, int k0, int ldw, int tid) {
    uint32_t stW = stA + A_BYTES;
#pragma unroll
    for (int it = 0; it < 4; ++it) {
        int u = tid + it * 256;
        int row = u >> 3, c4 = (u & 7) * 4;
        CP_ASYNC16(stA + (uint32_t)(row * A_PAD + c4) * 4u,
                   A + (size_t)(r0 + row) * HDIM + k0 + c4);
    }
#pragma unroll
    for (int it = 0; it < 4; ++it) {
        int u = tid + it * 256;
        int kr = u >> 5, c4 = (u & 31) * 4;
        CP_ASYNC16(stW + (uint32_t)(kr * W_PAD + c4) * 4u,
                   W + (size_t)(k0 + kr) * ldw + n0 + c4);
    }
}

// one k-chunk (BK=32) of mma work on a resident stage
__device__ __forceinline__ void compute_chunk(const float* __restrict__ As,
                                              const float* __restrict__ Ws,
                                              float acc[4][4][4],
                                              int wm, int wn, int g, int tg) {
#pragma unroll
    for (int kk = 0; kk < 4; ++kk) {
        uint32_t af[4][4], bw[4][2];
#pragma unroll
        for (int mf = 0; mf < 4; ++mf) {
            int br = wm * 64 + mf * 16;
            af[mf][0] = f2tf32(As[(br + g) * A_PAD + kk * 8 + tg]);
            af[mf][1] = f2tf32(As[(br + g + 8) * A_PAD + kk * 8 + tg]);
            af[mf][2] = f2tf32(As[(br + g) * A_PAD + kk * 8 + tg + 4]);
            af[mf][3] = f2tf32(As[(br + g + 8) * A_PAD + kk * 8 + tg + 4]);
        }
#pragma unroll
        for (int nf = 0; nf < 4; ++nf) {
            int bc = wn * 32 + nf * 8;
            bw[nf][0] = f2tf32(Ws[(kk * 8 + tg) * W_PAD + bc + g]);
            bw[nf][1] = f2tf32(Ws[(kk * 8 + tg + 4) * W_PAD + bc + g]);
        }
#pragma unroll
        for (int mf = 0; mf < 4; ++mf)
#pragma unroll
            for (int nf = 0; nf < 4; ++nf) mma_tf32(acc[mf][nf], af[mf], bw[nf]);
    }
}

// ---------------------------------------------------------------------------
// small kernels
// ---------------------------------------------------------------------------
__global__ void zero_stats_kernel() {
    int i = blockIdx.x * blockDim.x + threadIdx.x;
    if (i < BATCH * HDIM) g_Gacc[i] = 0.0f;
    if (i < BATCH) g_S[i] = 0.0f;
}

__global__ void prep_kernel(const float* __restrict__ Wp, const float* __restrict__ Wf,
                            const float* __restrict__ bp, const float* __restrict__ bf) {
    int j = threadIdx.x;
    if (blockIdx.x < 32) {
        __shared__ float Wp_s[16][512];
        int i0 = blockIdx.x * 16;
        for (int i = threadIdx.x; i < 16 * 512; i += 256)
            Wp_s[i >> 9][i & 511] = Wp[(size_t)(i0 + (i >> 9)) * 512 + (i & 511)];
        __syncthreads();
        float acc[16];
#pragma unroll
        for (int i = 0; i < 16; ++i) acc[i] = 0.0f;
        for (int k = 0; k < 512; ++k) {
            float wf = Wf[(size_t)k * TDIM + j];
#pragma unroll
            for (int i = 0; i < 16; ++i) acc[i] += Wp_s[i][k] * wf;
        }
#pragma unroll
        for (int i = 0; i < 16; ++i) g_Wpf[(size_t)(i0 + i) * TDIM + j] = acc[i];
    } else {
        __shared__ float bp_s[512];
        for (int i = threadIdx.x; i < 512; i += 256) bp_s[i] = bp[i];
        __syncthreads();
        float a = bf[j];
        for (int k = 0; k < 512; ++k) a += bp_s[k] * Wf[(size_t)k * TDIM + j];
        g_cpf[j] = a;
    }
}

__global__ void finalize_g_kernel() {
    int b = blockIdx.x, j = threadIdx.x;
    float denom = fmaxf(SCALE_F * sqrtf(g_S[b]), EPS_F);
    g_G[b * HDIM + j] = SCALE_F * g_Gacc[b * HDIM + j] / denom;
}

__global__ void build_wpfb_kernel() {
    int k = blockIdx.x, b = blockIdx.y, n = threadIdx.x;
    g_Wpfb[((size_t)b * HDIM + k) * TDIM + n] = g_G[b * HDIM + k] * g_Wpf[(size_t)k * TDIM + n];
}

// ---------------------------------------------------------------------------
// rowwise norms + qw + kn(in place) + per-batch reductions
// ---------------------------------------------------------------------------
__global__ void rowwise_kernel(const float* __restrict__ wg) {
    __shared__ float wg_s[512];
    __shared__ float Gs[8][512];
    __shared__ float Sq[8];
    const int tid = threadIdx.x, warp = tid >> 5, lane = tid & 31;
    const int r0 = blockIdx.x * 128;
    const int b = r0 >> 12;

    for (int i = tid; i < 512; i += 256) wg_s[i] = wg[i];
    for (int i = tid; i < 8 * 512; i += 256) (&Gs[0][0])[i] = 0.0f;
    __syncthreads();

    float qw2 = 0.0f;
    for (int rt = 0; rt < 16; ++rt) {
        int r = r0 + rt * 8 + warp;
        const float* qr = g_Q + (size_t)r * HDIM;
        float* kr = g_K + (size_t)r * HDIM;
        float q[16], k[16];
        float sq = 0.0f, sg = 0.0f, sk = 0.0f;
#pragma unroll
        for (int t = 0; t < 16; ++t) {
            int j = lane + 32 * t;
            q[t] = qr[j]; k[t] = kr[j];
            sq += q[t] * q[t]; sg += q[t] * wg_s[j]; sk += k[t] * k[t];
        }
#pragma unroll
        for (int o = 16; o; o >>= 1) {
            sq += __shfl_xor_sync(0xffffffffu, sq, o);
            sg += __shfl_xor_sync(0xffffffffu, sg, o);
            sk += __shfl_xor_sync(0xffffffffu, sk, o);
        }
        float dq = fmaxf(sqrtf(sq), EPS_F);
        float dk = fmaxf(sqrtf(sk), EPS_F);
        float qw = sg / dq;
        float rk = 1.0f / dk;
        qw2 += qw * qw;
#pragma unroll
        for (int t = 0; t < 16; ++t) {
            int j = lane + 32 * t;
            kr[j] = k[t] * rk;
            Gs[warp][j] += qw * q[t];
        }
    }
    if (lane == 0) Sq[warp] = qw2;
    __syncthreads();

    for (int j = tid; j < 512; j += 256) {
        float s = 0.0f;
#pragma unroll
        for (int w = 0; w < 8; ++w) s += Gs[w][j];
        atomicAdd(&g_Gacc[b * HDIM + j], s);
    }
    if (tid == 0) {
        float s = 0.0f;
#pragma unroll
        for (int w = 0; w < 8; ++w) s += Sq[w];
        atomicAdd(&g_S[b], s);
    }
}

// ---------------------------------------------------------------------------
// Fused Q/K GEMM: grid (8, 512). bx<4 -> Q cols [bx*128, ..], else K.
// 8 CTAs per row-block share the same A tile via L2.
// ---------------------------------------------------------------------------
__global__ __launch_bounds__(256, 2)
void qk_gemm_kernel(const float* __restrict__ x,
                    const float* __restrict__ Wq, const float* __restrict__ Wk,
                    const float* __restrict__ bq, const float* __restrict__ bk) {
    extern __shared__ char sm_raw[];
    const int bx = blockIdx.x;
    const float* W = (bx < 4) ? Wq : Wk;
    const float* bias = (bx < 4) ? bq : bk;
    float* C = (bx < 4) ? g_Q : g_K;
    const int n0 = (bx & 3) * 128;
    const int r0 = blockIdx.y * 128;
    const int tid = threadIdx.x, warp = tid >> 5, lane = tid & 31;
    const int wm = warp >> 2, wn = warp & 3, g = lane >> 2, tg = lane & 3;

    uint32_t smBase = smem_u32(sm_raw);
    float acc[4][4][4];
#pragma unroll
    for (int a = 0; a < 4; ++a)
#pragma unroll
        for (int b2 = 0; b2 < 4; ++b2)
#pragma unroll
            for (int c = 0; c < 4; ++c) acc[a][b2][c] = 0.0f;

    load_tile(smBase + 0 * STAGE_BYTES, x, W, r0, n0, 0, HDIM, tid);
    CP_COMMIT();
    load_tile(smBase + 1 * STAGE_BYTES, x, W, r0, n0, 32, HDIM, tid);
    CP_COMMIT();

    for (int c = 0; c < 16; ++c) {
        if (c + 2 < 16)
            load_tile(smBase + (uint32_t)((c + 2) % NSTG) * STAGE_BYTES, x, W, r0, n0,
                      (c + 2) * 32, HDIM, tid);
        CP_COMMIT();
        CP_WAIT2();
        __syncthreads();
        const float* As = (const float*)(sm_raw + (size_t)(c % NSTG) * STAGE_BYTES);
        const float* Ws = As + 128 * A_PAD;
        compute_chunk(As, Ws, acc, wm, wn, g, tg);
        __syncthreads();
    }

#pragma unroll
    for (int mf = 0; mf < 4; ++mf) {
#pragma unroll
        for (int nf = 0; nf < 4; ++nf) {
            int row = r0 + wm * 64 + mf * 16 + g;
            int col = n0 + wn * 32 + nf * 8 + tg * 2;
            float b0v = bias[col], b1v = bias[col + 1];
            C[(size_t)row * HDIM + col]           = acc[mf][nf][0] + b0v;
            C[(size_t)row * HDIM + col + 1]       = acc[mf][nf][1] + b1v;
            C[(size_t)(row + 8) * HDIM + col]     = acc[mf][nf][2] + b0v;
            C[(size_t)(row + 8) * HDIM + col + 1] = acc[mf][nf][3] + b1v;
        }
    }
}

// ---------------------------------------------------------------------------
// Final GEMM: out = Q@Wf + KN@Wpfb[batch] + cpf.  grid (2, 512), 2 passes K=512.
// ---------------------------------------------------------------------------
__global__ __launch_bounds__(256, 2)
void final_gemm_kernel(const float* __restrict__ Wf, float* __restrict__ out) {
    extern __shared__ char sm_raw[];
    const int n0 = blockIdx.x * 128;
    const int r0 = blockIdx.y * 128;
    const int batch = r0 >> 12;
    const float* A0 = g_Q;
    const float* W0 = Wf;
    const float* A1 = g_K;
    const float* W1 = g_Wpfb + (size_t)batch * HDIM * TDIM;
    const int tid = threadIdx.x, warp = tid >> 5, lane = tid & 31;
    const int wm = warp >> 2, wn = warp & 3, g = lane >> 2, tg = lane & 3;

    uint32_t smBase = smem_u32(sm_raw);
    float acc[4][4][4];
#pragma unroll
    for (int a = 0; a < 4; ++a)
#pragma unroll
        for (int b2 = 0; b2 < 4; ++b2)
#pragma unroll
            for (int c = 0; c < 4; ++c) acc[a][b2][c] = 0.0f;

    auto issue = [&](int c) {
        int pass = c >> 4, k0 = (c & 15) * 32;
        load_tile(smBase + (uint32_t)(c % NSTG) * STAGE_BYTES,
                  pass ? A1 : A0, pass ? W1 : W0, r0, n0, k0, TDIM, tid);
    };

    issue(0); CP_COMMIT();
    issue(1); CP_COMMIT();

    for (int c = 0; c < 32; ++c) {
        if (c + 2 < 32) issue(c + 2);
        CP_COMMIT();
        CP_WAIT2();
        __syncthreads();
        const float* As = (const float*)(sm_raw + (size_t)(c % NSTG) * STAGE_BYTES);
        const float* Ws = As + 128 * A_PAD;
        compute_chunk(As, Ws, acc, wm, wn, g, tg);
        __syncthreads();
    }

#pragma unroll
    for (int mf = 0; mf < 4; ++mf) {
#pragma unroll
        for (int nf = 0; nf < 4; ++nf) {
            int row = r0 + wm * 64 + mf * 16 + g;
            int col = n0 + wn * 32 + nf * 8 + tg * 2;
            float b0v = g_cpf[col], b1v = g_cpf[col + 1];
            out[(size_t)row * TDIM + col]           = acc[mf][nf][0] + b0v;
            out[(size_t)row * TDIM + col + 1]       = acc[mf][nf][1] + b1v;
            out[(size_t)(row + 8) * TDIM + col]     = acc[mf][nf][2] + b0v;
            out[(size_t)(row + 8) * TDIM + col + 1] = acc[mf][nf][3] + b1v;
        }
    }
}

// ---------------------------------------------------------------------------
extern "C" void kernel_launch(void* const* d_in, const int* in_sizes, int n_in,
                              void* d_out, int out_size) {
    const float* x  = (const float*)d_in[0];
    const float* Wq = (const float*)d_in[1];
    const float* bq = (const float*)d_in[2];
    const float* Wk = (const float*)d_in[3];
    const float* bk = (const float*)d_in[4];
    const float* wg = (const float*)d_in[5];
    const float* Wp = (const float*)d_in[6];
    const float* bp = (const float*)d_in[7];
    const float* Wf = (const float*)d_in[8];
    const float* bf = (const float*)d_in[9];
    float* out = (float*)d_out;

    cudaFuncSetAttribute(qk_gemm_kernel, cudaFuncAttributeMaxDynamicSharedMemorySize, SMEM_DYN);
    cudaFuncSetAttribute(final_gemm_kernel, cudaFuncAttributeMaxDynamicSharedMemorySize, SMEM_DYN);

    zero_stats_kernel<<<32, 256>>>();
    prep_kernel<<<33, 256>>>(Wp, Wf, bp, bf);
    qk_gemm_kernel<<<dim3(8, 512), 256, SMEM_DYN>>>(x, Wq, Wk, bq, bk);
    rowwise_kernel<<<512, 256>>>(wg);
    finalize_g_kernel<<<16, 512>>>();
    build_wpfb_kernel<<<dim3(512, 16), 256>>>();
    final_gemm_kernel<<<dim3(2, 512), 256, SMEM_DYN>>>(Wf, out);
}

// round 6
// speedup vs baseline: 1.6375x; 1.4095x over previous
#include <cuda_runtime.h>
#include <cuda_fp16.h>
#include <cstdint>

// ---------------------------------------------------------------------------
// EfficientAdditiveAttention — round 5 (resubmit of R4; infra failed):
// fp16 mma.m16n8k16 (same 11-bit mantissa as tf32), pre-converted operands,
// 64x64 warp tiles, 4-stage cp.async pipeline. All feeds single 4B LDS.
//
//   q = x@Wq + bq ; k = x@Wk + bk
//   qw = (q/||q||).w_g ; kn = k/||k||
//   S_b = sum qw^2 ; Gacc_b = sum qw*q ; G_b = SCALE*Gacc/max(SCALE*sqrt(S),EPS)
//   out = q@Wf + kn@(diag(G_b)·Wp@Wf) + (bp@Wf + bf)
// ---------------------------------------------------------------------------

#define BATCH   16
#define SEQ     4096
#define HDIM    512
#define TDIM    256
#define MTOT    (BATCH * SEQ)
#define EPS_F   1e-12f
#define SCALE_F 0.044194173824159216f

// ---------------- scratch (device globals; no runtime alloc) ---------------
__device__ __align__(16) __half g_Xh[(size_t)MTOT * HDIM];     // x in fp16
__device__ __align__(16) __half g_Qh[(size_t)MTOT * HDIM];     // q fp16
__device__ __align__(16) __half g_Kh[(size_t)MTOT * HDIM];     // k -> kn fp16
__device__ __align__(16) __half g_WqT[HDIM * HDIM];            // Wq^T [n][k]
__device__ __align__(16) __half g_WkT[HDIM * HDIM];
__device__ __align__(16) __half g_WfT[TDIM * HDIM];            // Wf^T [256][512]
__device__ __align__(16) __half g_WpfbT[(size_t)BATCH * TDIM * HDIM]; // (diag(G)Wpf)^T
__device__ float g_Wpf[HDIM * TDIM];                           // Wp@Wf fp32
__device__ float g_cpf[TDIM];
__device__ float g_Gacc[BATCH * HDIM];
__device__ float g_S[BATCH];
__device__ float g_G[BATCH * HDIM];

// ---------------------------- helpers --------------------------------------
__device__ __forceinline__ uint32_t smem_u32(const void* p) {
    uint32_t a;
    asm("{ .reg .u64 t; cvta.to.shared.u64 t, %1; cvt.u32.u64 %0, t; }" : "=r"(a) : "l"(p));
    return a;
}

#define CP_ASYNC16(dst, src) \
    asm volatile("cp.async.cg.shared.global [%0], [%1], 16;" :: "r"(dst), "l"(src) : "memory")
#define CP_COMMIT() asm volatile("cp.async.commit_group;" ::: "memory")
#define CP_WAIT3()  asm volatile("cp.async.wait_group 3;" ::: "memory")

__device__ __forceinline__ void mma_f16(float c[4], const uint32_t a[4], const uint32_t b[2]) {
    asm volatile(
        "mma.sync.aligned.m16n8k16.row.col.f32.f16.f16.f32 "
        "{%0,%1,%2,%3}, {%4,%5,%6,%7}, {%8,%9}, {%0,%1,%2,%3};\n"
        : "+f"(c[0]), "+f"(c[1]), "+f"(c[2]), "+f"(c[3])
        : "r"(a[0]), "r"(a[1]), "r"(a[2]), "r"(a[3]), "r"(b[0]), "r"(b[1]));
}

// stage geometry (halves): A tile 128x32 pad ld=40; W tile 256x32 pad ld=40
#define LDT 40
#define A_BYTES (128 * LDT * 2)                 // 10240
#define W_BYTES (256 * LDT * 2)                 // 20480
#define STAGE_BYTES (A_BYTES + W_BYTES)         // 30720
#define NSTG 4
#define SMEM_DYN (NSTG * STAGE_BYTES)           // 122880

// load one (A 128x32, W 256x32) chunk of halves into a stage
__device__ __forceinline__ void load_tile(uint32_t stA, const __half* __restrict__ A,
                                          const __half* __restrict__ Wt,
                                          int r0, int n0, int k0, int tid) {
    uint32_t stW = stA + A_BYTES;
#pragma unroll
    for (int it = 0; it < 2; ++it) {            // A: 128 rows x 4 chunks = 512
        int u = tid + it * 256;
        int row = u >> 2, c = u & 3;
        CP_ASYNC16(stA + (uint32_t)(row * LDT * 2 + c * 16),
                   A + (size_t)(r0 + row) * HDIM + k0 + c * 8);
    }
#pragma unroll
    for (int it = 0; it < 4; ++it) {            // W: 256 rows x 4 chunks = 1024
        int u = tid + it * 256;
        int row = u >> 2, c = u & 3;
        CP_ASYNC16(stW + (uint32_t)(row * LDT * 2 + c * 16),
                   Wt + (size_t)(n0 + row) * HDIM + k0 + c * 8);
    }
}

// one BK=32 chunk: 2 k16 steps, warp tile 64x64 (4 mf x 8 nf)
__device__ __forceinline__ void compute_chunk(const __half* __restrict__ As,
                                              const __half* __restrict__ Ws,
                                              float acc[4][8][4],
                                              int wm, int wn, int g, int tg) {
#pragma unroll
    for (int ks = 0; ks < 2; ++ks) {
        int kb = ks * 16;
        uint32_t af[4][4], bw[8][2];
#pragma unroll
        for (int mf = 0; mf < 4; ++mf) {
            int br = wm * 64 + mf * 16;
            af[mf][0] = *(const uint32_t*)(As + (br + g) * LDT + kb + 2 * tg);
            af[mf][1] = *(const uint32_t*)(As + (br + g + 8) * LDT + kb + 2 * tg);
            af[mf][2] = *(const uint32_t*)(As + (br + g) * LDT + kb + 2 * tg + 8);
            af[mf][3] = *(const uint32_t*)(As + (br + g + 8) * LDT + kb + 2 * tg + 8);
        }
#pragma unroll
        for (int nf = 0; nf < 8; ++nf) {
            int bc = wn * 64 + nf * 8;
            bw[nf][0] = *(const uint32_t*)(Ws + (bc + g) * LDT + kb + 2 * tg);
            bw[nf][1] = *(const uint32_t*)(Ws + (bc + g) * LDT + kb + 2 * tg + 8);
        }
#pragma unroll
        for (int mf = 0; mf < 4; ++mf)
#pragma unroll
            for (int nf = 0; nf < 8; ++nf) mma_f16(acc[mf][nf], af[mf], bw[nf]);
    }
}

// ---------------------------------------------------------------------------
// small kernels
// ---------------------------------------------------------------------------
__global__ void zero_stats_kernel() {
    int i = blockIdx.x * blockDim.x + threadIdx.x;
    if (i < BATCH * HDIM) g_Gacc[i] = 0.0f;
    if (i < BATCH) g_S[i] = 0.0f;
}

__global__ void conv_x_kernel(const float* __restrict__ x) {
    size_t n4 = (size_t)MTOT * HDIM / 4;
    __half2* dst = reinterpret_cast<__half2*>(g_Xh);
    for (size_t i = blockIdx.x * blockDim.x + threadIdx.x; i < n4;
         i += (size_t)gridDim.x * blockDim.x) {
        float4 v = reinterpret_cast<const float4*>(x)[i];
        dst[2 * i]     = __floats2half2_rn(v.x, v.y);
        dst[2 * i + 1] = __floats2half2_rn(v.z, v.w);
    }
}

// dst[n][k] = half(src[k][n]); src rows=K, cols=N (n contiguous)
__global__ void transpose_h_kernel(const float* __restrict__ src, __half* __restrict__ dst,
                                   int rows, int cols) {
    __shared__ float t[32][33];
    int x0 = blockIdx.x * 32, y0 = blockIdx.y * 32;
    int tx = threadIdx.x, ty = threadIdx.y;
#pragma unroll
    for (int i = 0; i < 4; ++i)
        t[ty + 8 * i][tx] = src[(size_t)(y0 + ty + 8 * i) * cols + x0 + tx];
    __syncthreads();
#pragma unroll
    for (int i = 0; i < 4; ++i)
        dst[(size_t)(x0 + ty + 8 * i) * rows + y0 + tx] = __float2half_rn(t[tx][ty + 8 * i]);
}

__global__ void prep_kernel(const float* __restrict__ Wp, const float* __restrict__ Wf,
                            const float* __restrict__ bp, const float* __restrict__ bf) {
    int j = threadIdx.x;
    if (blockIdx.x < 32) {
        __shared__ float Wp_s[16][512];
        int i0 = blockIdx.x * 16;
        for (int i = threadIdx.x; i < 16 * 512; i += 256)
            Wp_s[i >> 9][i & 511] = Wp[(size_t)(i0 + (i >> 9)) * 512 + (i & 511)];
        __syncthreads();
        float acc[16];
#pragma unroll
        for (int i = 0; i < 16; ++i) acc[i] = 0.0f;
        for (int k = 0; k < 512; ++k) {
            float wf = Wf[(size_t)k * TDIM + j];
#pragma unroll
            for (int i = 0; i < 16; ++i) acc[i] += Wp_s[i][k] * wf;
        }
#pragma unroll
        for (int i = 0; i < 16; ++i) g_Wpf[(size_t)(i0 + i) * TDIM + j] = acc[i];
    } else {
        __shared__ float bp_s[512];
        for (int i = threadIdx.x; i < 512; i += 256) bp_s[i] = bp[i];
        __syncthreads();
        float a = bf[j];
        for (int k = 0; k < 512; ++k) a += bp_s[k] * Wf[(size_t)k * TDIM + j];
        g_cpf[j] = a;
    }
}

__global__ void finalize_g_kernel() {
    int b = blockIdx.x, j = threadIdx.x;
    float denom = fmaxf(SCALE_F * sqrtf(g_S[b]), EPS_F);
    g_G[b * HDIM + j] = SCALE_F * g_Gacc[b * HDIM + j] / denom;
}

// WpfbT[b][n][k] = half(G[b][k] * Wpf[k][n])   grid(256,16) block 512
__global__ void build_wpfbt_kernel() {
    int n = blockIdx.x, b = blockIdx.y, k = threadIdx.x;
    g_WpfbT[((size_t)b * TDIM + n) * HDIM + k] =
        __float2half_rn(g_G[b * HDIM + k] * g_Wpf[(size_t)k * TDIM + n]);
}

// ---------------------------------------------------------------------------
// rowwise: norms + qw + kn(in place, half) + per-batch reductions (half I/O)
// ---------------------------------------------------------------------------
__global__ void rowwise_kernel(const float* __restrict__ wg) {
    __shared__ float wg_s[512];
    __shared__ float Gs[8][512];
    __shared__ float Sq[8];
    const int tid = threadIdx.x, warp = tid >> 5, lane = tid & 31;
    const int r0 = blockIdx.x * 128;
    const int b = r0 >> 12;

    for (int i = tid; i < 512; i += 256) wg_s[i] = wg[i];
    for (int i = tid; i < 8 * 512; i += 256) (&Gs[0][0])[i] = 0.0f;
    __syncthreads();

    float qw2 = 0.0f;
    for (int rt = 0; rt < 16; ++rt) {
        int r = r0 + rt * 8 + warp;
        const __half2* qr = reinterpret_cast<const __half2*>(g_Qh + (size_t)r * HDIM);
        __half2* kr = reinterpret_cast<__half2*>(g_Kh + (size_t)r * HDIM);
        float2 q[8], k[8];
        float sq = 0.0f, sg = 0.0f, sk = 0.0f;
#pragma unroll
        for (int t = 0; t < 8; ++t) {
            int j2 = lane + 32 * t;
            q[t] = __half22float2(qr[j2]);
            k[t] = __half22float2(kr[j2]);
            sq += q[t].x * q[t].x + q[t].y * q[t].y;
            sk += k[t].x * k[t].x + k[t].y * k[t].y;
            sg += q[t].x * wg_s[2 * j2] + q[t].y * wg_s[2 * j2 + 1];
        }
#pragma unroll
        for (int o = 16; o; o >>= 1) {
            sq += __shfl_xor_sync(0xffffffffu, sq, o);
            sg += __shfl_xor_sync(0xffffffffu, sg, o);
            sk += __shfl_xor_sync(0xffffffffu, sk, o);
        }
        float dq = fmaxf(sqrtf(sq), EPS_F);
        float dk = fmaxf(sqrtf(sk), EPS_F);
        float qw = sg / dq;
        float rk = 1.0f / dk;
        qw2 += qw * qw;
#pragma unroll
        for (int t = 0; t < 8; ++t) {
            int j2 = lane + 32 * t;
            kr[j2] = __floats2half2_rn(k[t].x * rk, k[t].y * rk);
            Gs[warp][2 * j2]     += qw * q[t].x;
            Gs[warp][2 * j2 + 1] += qw * q[t].y;
        }
    }
    if (lane == 0) Sq[warp] = qw2;
    __syncthreads();

    for (int j = tid; j < 512; j += 256) {
        float s = 0.0f;
#pragma unroll
        for (int w = 0; w < 8; ++w) s += Gs[w][j];
        atomicAdd(&g_Gacc[b * HDIM + j], s);
    }
    if (tid == 0) {
        float s = 0.0f;
#pragma unroll
        for (int w = 0; w < 8; ++w) s += Sq[w];
        atomicAdd(&g_S[b], s);
    }
}

// ---------------------------------------------------------------------------
// Fused Q/K GEMM (fp16): grid (4, 512). bx<2 -> Q (n0=bx*256), else K.
// CTA tile 128x256, warp tile 64x64, BK=32, 4-stage cp.async.
// ---------------------------------------------------------------------------
__global__ __launch_bounds__(256, 1)
void qk_gemm_kernel(const float* __restrict__ bq, const float* __restrict__ bk) {
    extern __shared__ char sm_raw[];
    const int bx = blockIdx.x;
    const bool isQ = (bx < 2);
    const __half* Wt = isQ ? g_WqT : g_WkT;
    const float* bias = isQ ? bq : bk;
    __half* C = isQ ? g_Qh : g_Kh;
    const int n0 = (bx & 1) * 256;
    const int r0 = blockIdx.y * 128;
    const int tid = threadIdx.x, warp = tid >> 5, lane = tid & 31;
    const int wm = warp >> 2, wn = warp & 3, g = lane >> 2, tg = lane & 3;

    uint32_t smBase = smem_u32(sm_raw);
    float acc[4][8][4];
#pragma unroll
    for (int a = 0; a < 4; ++a)
#pragma unroll
        for (int b2 = 0; b2 < 8; ++b2)
#pragma unroll
            for (int c = 0; c < 4; ++c) acc[a][b2][c] = 0.0f;

    load_tile(smBase + 0 * STAGE_BYTES, g_Xh, Wt, r0, n0, 0, tid);  CP_COMMIT();
    load_tile(smBase + 1 * STAGE_BYTES, g_Xh, Wt, r0, n0, 32, tid); CP_COMMIT();
    load_tile(smBase + 2 * STAGE_BYTES, g_Xh, Wt, r0, n0, 64, tid); CP_COMMIT();

    for (int c = 0; c < 16; ++c) {
        if (c + 3 < 16)
            load_tile(smBase + (uint32_t)((c + 3) % NSTG) * STAGE_BYTES, g_Xh, Wt,
                      r0, n0, (c + 3) * 32, tid);
        CP_COMMIT();
        CP_WAIT3();
        __syncthreads();
        const __half* As = (const __half*)(sm_raw + (size_t)(c % NSTG) * STAGE_BYTES);
        const __half* Ws = As + 128 * LDT;
        compute_chunk(As, Ws, acc, wm, wn, g, tg);
        __syncthreads();
    }

#pragma unroll
    for (int mf = 0; mf < 4; ++mf) {
#pragma unroll
        for (int nf = 0; nf < 8; ++nf) {
            int row = r0 + wm * 64 + mf * 16 + g;
            int col = n0 + wn * 64 + nf * 8 + tg * 2;
            float b0v = bias[col], b1v = bias[col + 1];
            *reinterpret_cast<__half2*>(&C[(size_t)row * HDIM + col]) =
                __floats2half2_rn(acc[mf][nf][0] + b0v, acc[mf][nf][1] + b1v);
            *reinterpret_cast<__half2*>(&C[(size_t)(row + 8) * HDIM + col]) =
                __floats2half2_rn(acc[mf][nf][2] + b0v, acc[mf][nf][3] + b1v);
        }
    }
}

// ---------------------------------------------------------------------------
// Final GEMM (fp16): out = Q@Wf + KN@Wpfb[batch] + cpf.  grid (1, 512).
// 2 passes of K=512 accumulated into one 128x256 tile.
// ---------------------------------------------------------------------------
__global__ __launch_bounds__(256, 1)
void final_gemm_kernel(float* __restrict__ out) {
    extern __shared__ char sm_raw[];
    const int r0 = blockIdx.y * 128;
    const int batch = r0 >> 12;
    const __half* W1 = g_WpfbT + (size_t)batch * TDIM * HDIM;
    const int tid = threadIdx.x, warp = tid >> 5, lane = tid & 31;
    const int wm = warp >> 2, wn = warp & 3, g = lane >> 2, tg = lane & 3;

    uint32_t smBase = smem_u32(sm_raw);
    float acc[4][8][4];
#pragma unroll
    for (int a = 0; a < 4; ++a)
#pragma unroll
        for (int b2 = 0; b2 < 8; ++b2)
#pragma unroll
            for (int c = 0; c < 4; ++c) acc[a][b2][c] = 0.0f;

    auto issue = [&](int c) {
        int pass = c >> 4, k0 = (c & 15) * 32;
        load_tile(smBase + (uint32_t)(c % NSTG) * STAGE_BYTES,
                  pass ? g_Kh : g_Qh, pass ? W1 : g_WfT, r0, 0, k0, tid);
    };

    issue(0); CP_COMMIT();
    issue(1); CP_COMMIT();
    issue(2); CP_COMMIT();

    for (int c = 0; c < 32; ++c) {
        if (c + 3 < 32) issue(c + 3);
        CP_COMMIT();
        CP_WAIT3();
        __syncthreads();
        const __half* As = (const __half*)(sm_raw + (size_t)(c % NSTG) * STAGE_BYTES);
        const __half* Ws = As + 128 * LDT;
        compute_chunk(As, Ws, acc, wm, wn, g, tg);
        __syncthreads();
    }

#pragma unroll
    for (int mf = 0; mf < 4; ++mf) {
#pragma unroll
        for (int nf = 0; nf < 8; ++nf) {
            int row = r0 + wm * 64 + mf * 16 + g;
            int col = wn * 64 + nf * 8 + tg * 2;
            float b0v = g_cpf[col], b1v = g_cpf[col + 1];
            *reinterpret_cast<float2*>(&out[(size_t)row * TDIM + col]) =
                make_float2(acc[mf][nf][0] + b0v, acc[mf][nf][1] + b1v);
            *reinterpret_cast<float2*>(&out[(size_t)(row + 8) * TDIM + col]) =
                make_float2(acc[mf][nf][2] + b0v, acc[mf][nf][3] + b1v);
        }
    }
}

// ---------------------------------------------------------------------------
extern "C" void kernel_launch(void* const* d_in, const int* in_sizes, int n_in,
                              void* d_out, int out_size) {
    const float* x  = (const float*)d_in[0];
    const float* Wq = (const float*)d_in[1];
    const float* bq = (const float*)d_in[2];
    const float* Wk = (const float*)d_in[3];
    const float* bk = (const float*)d_in[4];
    const float* wg = (const float*)d_in[5];
    const float* Wp = (const float*)d_in[6];
    const float* bp = (const float*)d_in[7];
    const float* Wf = (const float*)d_in[8];
    const float* bf = (const float*)d_in[9];
    float* out = (float*)d_out;

    cudaFuncSetAttribute(qk_gemm_kernel, cudaFuncAttributeMaxDynamicSharedMemorySize, SMEM_DYN);
    cudaFuncSetAttribute(final_gemm_kernel, cudaFuncAttributeMaxDynamicSharedMemorySize, SMEM_DYN);

    __half* pWqT; cudaGetSymbolAddress((void**)&pWqT, g_WqT);
    __half* pWkT; cudaGetSymbolAddress((void**)&pWkT, g_WkT);
    __half* pWfT; cudaGetSymbolAddress((void**)&pWfT, g_WfT);

    zero_stats_kernel<<<32, 256>>>();
    conv_x_kernel<<<2048, 256>>>(x);
    transpose_h_kernel<<<dim3(16, 16), dim3(32, 8)>>>(Wq, pWqT, 512, 512);
    transpose_h_kernel<<<dim3(16, 16), dim3(32, 8)>>>(Wk, pWkT, 512, 512);
    transpose_h_kernel<<<dim3(8, 16), dim3(32, 8)>>>(Wf, pWfT, 512, 256);
    prep_kernel<<<33, 256>>>(Wp, Wf, bp, bf);

    qk_gemm_kernel<<<dim3(4, 512), 256, SMEM_DYN>>>(bq, bk);

    rowwise_kernel<<<512, 256>>>(wg);
    finalize_g_kernel<<<16, 512>>>();
    build_wpfbt_kernel<<<dim3(256, 16), 512>>>();

    final_gemm_kernel<<<dim3(1, 512), 256, SMEM_DYN>>>(out);
}

// round 8
// speedup vs baseline: 1.8042x; 1.1018x over previous
#include <cuda_runtime.h>
#include <cuda_fp16.h>
#include <cstdint>

// ---------------------------------------------------------------------------
// EfficientAdditiveAttention — round 8 (resubmit of R7; infra failed twice):
// fp16 mma.m16n8k16, BK=64 chunks, single-barrier pipelined mainloop
// (3 stages x 54KB), 64x64 warp tiles.
//
//   q = x@Wq + bq ; k = x@Wk + bk
//   qw = (q/||q||).w_g ; kn = k/||k||
//   S_b = sum qw^2 ; Gacc_b = sum qw*q ; G_b = SCALE*Gacc/max(SCALE*sqrt(S),EPS)
//   out = q@Wf + kn@(diag(G_b)·Wp@Wf) + (bp@Wf + bf)
// ---------------------------------------------------------------------------

#define BATCH   16
#define SEQ     4096
#define HDIM    512
#define TDIM    256
#define MTOT    (BATCH * SEQ)
#define EPS_F   1e-12f
#define SCALE_F 0.044194173824159216f

// ---------------- scratch (device globals; no runtime alloc) ---------------
__device__ __align__(16) __half g_Xh[(size_t)MTOT * HDIM];     // x in fp16
__device__ __align__(16) __half g_Qh[(size_t)MTOT * HDIM];     // q fp16
__device__ __align__(16) __half g_Kh[(size_t)MTOT * HDIM];     // k -> kn fp16
__device__ __align__(16) __half g_WqT[HDIM * HDIM];            // Wq^T [n][k]
__device__ __align__(16) __half g_WkT[HDIM * HDIM];
__device__ __align__(16) __half g_WfT[TDIM * HDIM];            // Wf^T [256][512]
__device__ __align__(16) __half g_WpfbT[(size_t)BATCH * TDIM * HDIM]; // (diag(G)Wpf)^T
__device__ float g_Wpf[HDIM * TDIM];                           // Wp@Wf fp32
__device__ float g_cpf[TDIM];
__device__ float g_Gacc[BATCH * HDIM];
__device__ float g_S[BATCH];
__device__ float g_G[BATCH * HDIM];

// ---------------------------- helpers --------------------------------------
__device__ __forceinline__ uint32_t smem_u32(const void* p) {
    uint32_t a;
    asm("{ .reg .u64 t; cvta.to.shared.u64 t, %1; cvt.u32.u64 %0, t; }" : "=r"(a) : "l"(p));
    return a;
}

#define CP_ASYNC16(dst, src) \
    asm volatile("cp.async.cg.shared.global [%0], [%1], 16;" :: "r"(dst), "l"(src) : "memory")
#define CP_COMMIT() asm volatile("cp.async.commit_group;" ::: "memory")
#define CP_WAIT1()  asm volatile("cp.async.wait_group 1;" ::: "memory")

__device__ __forceinline__ void mma_f16(float c[4], const uint32_t a[4], const uint32_t b[2]) {
    asm volatile(
        "mma.sync.aligned.m16n8k16.row.col.f32.f16.f16.f32 "
        "{%0,%1,%2,%3}, {%4,%5,%6,%7}, {%8,%9}, {%0,%1,%2,%3};\n"
        : "+f"(c[0]), "+f"(c[1]), "+f"(c[2]), "+f"(c[3])
        : "r"(a[0]), "r"(a[1]), "r"(a[2]), "r"(a[3]), "r"(b[0]), "r"(b[1]));
}

// stage geometry (halves): BK=64. A tile 128x64 ld=72; W tile 256x64 ld=72.
// bank check: word index (row*72 + 2*tg) -> bank (4*g + tg), all 32 distinct.
#define LDT 72
#define A_BYTES (128 * LDT * 2)                 // 18432
#define W_BYTES (256 * LDT * 2)                 // 36864
#define STAGE_BYTES (A_BYTES + W_BYTES)         // 55296
#define NSTG 3
#define SMEM_DYN (NSTG * STAGE_BYTES)           // 165888

// load one (A 128x64, W 256x64) chunk of halves into a stage
__device__ __forceinline__ void load_tile(uint32_t stA, const __half* __restrict__ A,
                                          const __half* __restrict__ Wt,
                                          int r0, int n0, int k0, int tid) {
    uint32_t stW = stA + A_BYTES;
#pragma unroll
    for (int it = 0; it < 4; ++it) {            // A: 128 rows x 8 chunks = 1024
        int u = tid + it * 256;
        int row = u >> 3, c = u & 7;
        CP_ASYNC16(stA + (uint32_t)(row * LDT * 2 + c * 16),
                   A + (size_t)(r0 + row) * HDIM + k0 + c * 8);
    }
#pragma unroll
    for (int it = 0; it < 8; ++it) {            // W: 256 rows x 8 chunks = 2048
        int u = tid + it * 256;
        int row = u >> 3, c = u & 7;
        CP_ASYNC16(stW + (uint32_t)(row * LDT * 2 + c * 16),
                   Wt + (size_t)(n0 + row) * HDIM + k0 + c * 8);
    }
}

// one BK=64 chunk: 4 k16 steps, warp tile 64x64 (4 mf x 8 nf)
__device__ __forceinline__ void compute_chunk(const __half* __restrict__ As,
                                              const __half* __restrict__ Ws,
                                              float acc[4][8][4],
                                              int wm, int wn, int g, int tg) {
#pragma unroll
    for (int ks = 0; ks < 4; ++ks) {
        int kb = ks * 16;
        uint32_t af[4][4], bw[8][2];
#pragma unroll
        for (int mf = 0; mf < 4; ++mf) {
            int br = wm * 64 + mf * 16;
            af[mf][0] = *(const uint32_t*)(As + (br + g) * LDT + kb + 2 * tg);
            af[mf][1] = *(const uint32_t*)(As + (br + g + 8) * LDT + kb + 2 * tg);
            af[mf][2] = *(const uint32_t*)(As + (br + g) * LDT + kb + 2 * tg + 8);
            af[mf][3] = *(const uint32_t*)(As + (br + g + 8) * LDT + kb + 2 * tg + 8);
        }
#pragma unroll
        for (int nf = 0; nf < 8; ++nf) {
            int bc = wn * 64 + nf * 8;
            bw[nf][0] = *(const uint32_t*)(Ws + (bc + g) * LDT + kb + 2 * tg);
            bw[nf][1] = *(const uint32_t*)(Ws + (bc + g) * LDT + kb + 2 * tg + 8);
        }
#pragma unroll
        for (int mf = 0; mf < 4; ++mf)
#pragma unroll
            for (int nf = 0; nf < 8; ++nf) mma_f16(acc[mf][nf], af[mf], bw[nf]);
    }
}

// ---------------------------------------------------------------------------
// small kernels
// ---------------------------------------------------------------------------
__global__ void zero_stats_kernel() {
    int i = blockIdx.x * blockDim.x + threadIdx.x;
    if (i < BATCH * HDIM) g_Gacc[i] = 0.0f;
    if (i < BATCH) g_S[i] = 0.0f;
}

__global__ void conv_x_kernel(const float* __restrict__ x) {
    size_t n4 = (size_t)MTOT * HDIM / 4;
    __half2* dst = reinterpret_cast<__half2*>(g_Xh);
    for (size_t i = blockIdx.x * blockDim.x + threadIdx.x; i < n4;
         i += (size_t)gridDim.x * blockDim.x) {
        float4 v = reinterpret_cast<const float4*>(x)[i];
        dst[2 * i]     = __floats2half2_rn(v.x, v.y);
        dst[2 * i + 1] = __floats2half2_rn(v.z, v.w);
    }
}

// dst[n][k] = half(src[k][n]); src rows=K, cols=N (n contiguous)
__global__ void transpose_h_kernel(const float* __restrict__ src, __half* __restrict__ dst,
                                   int rows, int cols) {
    __shared__ float t[32][33];
    int x0 = blockIdx.x * 32, y0 = blockIdx.y * 32;
    int tx = threadIdx.x, ty = threadIdx.y;
#pragma unroll
    for (int i = 0; i < 4; ++i)
        t[ty + 8 * i][tx] = src[(size_t)(y0 + ty + 8 * i) * cols + x0 + tx];
    __syncthreads();
#pragma unroll
    for (int i = 0; i < 4; ++i)
        dst[(size_t)(x0 + ty + 8 * i) * rows + y0 + tx] = __float2half_rn(t[tx][ty + 8 * i]);
}

__global__ void prep_kernel(const float* __restrict__ Wp, const float* __restrict__ Wf,
                            const float* __restrict__ bp, const float* __restrict__ bf) {
    int j = threadIdx.x;
    if (blockIdx.x < 32) {
        __shared__ float Wp_s[16][512];
        int i0 = blockIdx.x * 16;
        for (int i = threadIdx.x; i < 16 * 512; i += 256)
            Wp_s[i >> 9][i & 511] = Wp[(size_t)(i0 + (i >> 9)) * 512 + (i & 511)];
        __syncthreads();
        float acc[16];
#pragma unroll
        for (int i = 0; i < 16; ++i) acc[i] = 0.0f;
        for (int k = 0; k < 512; ++k) {
            float wf = Wf[(size_t)k * TDIM + j];
#pragma unroll
            for (int i = 0; i < 16; ++i) acc[i] += Wp_s[i][k] * wf;
        }
#pragma unroll
        for (int i = 0; i < 16; ++i) g_Wpf[(size_t)(i0 + i) * TDIM + j] = acc[i];
    } else {
        __shared__ float bp_s[512];
        for (int i = threadIdx.x; i < 512; i += 256) bp_s[i] = bp[i];
        __syncthreads();
        float a = bf[j];
        for (int k = 0; k < 512; ++k) a += bp_s[k] * Wf[(size_t)k * TDIM + j];
        g_cpf[j] = a;
    }
}

__global__ void finalize_g_kernel() {
    int b = blockIdx.x, j = threadIdx.x;
    float denom = fmaxf(SCALE_F * sqrtf(g_S[b]), EPS_F);
    g_G[b * HDIM + j] = SCALE_F * g_Gacc[b * HDIM + j] / denom;
}

// WpfbT[b][n][k] = half(G[b][k] * Wpf[k][n])   grid(256,16) block 512
__global__ void build_wpfbt_kernel() {
    int n = blockIdx.x, b = blockIdx.y, k = threadIdx.x;
    g_WpfbT[((size_t)b * TDIM + n) * HDIM + k] =
        __float2half_rn(g_G[b * HDIM + k] * g_Wpf[(size_t)k * TDIM + n]);
}

// ---------------------------------------------------------------------------
// rowwise: norms + qw + kn(in place, half) + per-batch reductions (half I/O)
// ---------------------------------------------------------------------------
__global__ void rowwise_kernel(const float* __restrict__ wg) {
    __shared__ float wg_s[512];
    __shared__ float Gs[8][512];
    __shared__ float Sq[8];
    const int tid = threadIdx.x, warp = tid >> 5, lane = tid & 31;
    const int r0 = blockIdx.x * 128;
    const int b = r0 >> 12;

    for (int i = tid; i < 512; i += 256) wg_s[i] = wg[i];
    for (int i = tid; i < 8 * 512; i += 256) (&Gs[0][0])[i] = 0.0f;
    __syncthreads();

    float qw2 = 0.0f;
    for (int rt = 0; rt < 16; ++rt) {
        int r = r0 + rt * 8 + warp;
        const __half2* qr = reinterpret_cast<const __half2*>(g_Qh + (size_t)r * HDIM);
        __half2* kr = reinterpret_cast<__half2*>(g_Kh + (size_t)r * HDIM);
        float2 q[8], k[8];
        float sq = 0.0f, sg = 0.0f, sk = 0.0f;
#pragma unroll
        for (int t = 0; t < 8; ++t) {
            int j2 = lane + 32 * t;
            q[t] = __half22float2(qr[j2]);
            k[t] = __half22float2(kr[j2]);
            sq += q[t].x * q[t].x + q[t].y * q[t].y;
            sk += k[t].x * k[t].x + k[t].y * k[t].y;
            sg += q[t].x * wg_s[2 * j2] + q[t].y * wg_s[2 * j2 + 1];
        }
#pragma unroll
        for (int o = 16; o; o >>= 1) {
            sq += __shfl_xor_sync(0xffffffffu, sq, o);
            sg += __shfl_xor_sync(0xffffffffu, sg, o);
            sk += __shfl_xor_sync(0xffffffffu, sk, o);
        }
        float dq = fmaxf(sqrtf(sq), EPS_F);
        float dk = fmaxf(sqrtf(sk), EPS_F);
        float qw = sg / dq;
        float rk = 1.0f / dk;
        qw2 += qw * qw;
#pragma unroll
        for (int t = 0; t < 8; ++t) {
            int j2 = lane + 32 * t;
            kr[j2] = __floats2half2_rn(k[t].x * rk, k[t].y * rk);
            Gs[warp][2 * j2]     += qw * q[t].x;
            Gs[warp][2 * j2 + 1] += qw * q[t].y;
        }
    }
    if (lane == 0) Sq[warp] = qw2;
    __syncthreads();

    for (int j = tid; j < 512; j += 256) {
        float s = 0.0f;
#pragma unroll
        for (int w = 0; w < 8; ++w) s += Gs[w][j];
        atomicAdd(&g_Gacc[b * HDIM + j], s);
    }
    if (tid == 0) {
        float s = 0.0f;
#pragma unroll
        for (int w = 0; w < 8; ++w) s += Sq[w];
        atomicAdd(&g_S[b], s);
    }
}

// ---------------------------------------------------------------------------
// Fused Q/K GEMM (fp16): grid (4, 512). bx<2 -> Q (n0=bx*256), else K.
// CTA 128x256, warp 64x64, BK=64, 3-stage cp.async, ONE barrier per chunk.
// ---------------------------------------------------------------------------
__global__ __launch_bounds__(256, 1)
void qk_gemm_kernel(const float* __restrict__ bq, const float* __restrict__ bk) {
    extern __shared__ char sm_raw[];
    const int bx = blockIdx.x;
    const bool isQ = (bx < 2);
    const __half* Wt = isQ ? g_WqT : g_WkT;
    const float* bias = isQ ? bq : bk;
    __half* C = isQ ? g_Qh : g_Kh;
    const int n0 = (bx & 1) * 256;
    const int r0 = blockIdx.y * 128;
    const int tid = threadIdx.x, warp = tid >> 5, lane = tid & 31;
    const int wm = warp >> 2, wn = warp & 3, g = lane >> 2, tg = lane & 3;

    uint32_t smBase = smem_u32(sm_raw);
    float acc[4][8][4];
#pragma unroll
    for (int a = 0; a < 4; ++a)
#pragma unroll
        for (int b2 = 0; b2 < 8; ++b2)
#pragma unroll
            for (int c = 0; c < 4; ++c) acc[a][b2][c] = 0.0f;

    load_tile(smBase + 0 * STAGE_BYTES, g_Xh, Wt, r0, n0, 0, tid);  CP_COMMIT();
    load_tile(smBase + 1 * STAGE_BYTES, g_Xh, Wt, r0, n0, 64, tid); CP_COMMIT();

    const int TOT = 8;                                   // K=512 / BK=64
    for (int c = 0; c < TOT; ++c) {
        CP_WAIT1();                                      // chunk c resident
        __syncthreads();                                 // all warps done with c-1
        if (c + 2 < TOT) {
            load_tile(smBase + (uint32_t)((c + 2) % NSTG) * STAGE_BYTES, g_Xh, Wt,
                      r0, n0, (c + 2) * 64, tid);
            CP_COMMIT();
        }
        const __half* As = (const __half*)(sm_raw + (size_t)(c % NSTG) * STAGE_BYTES);
        const __half* Ws = As + 128 * LDT;
        compute_chunk(As, Ws, acc, wm, wn, g, tg);
    }

#pragma unroll
    for (int mf = 0; mf < 4; ++mf) {
#pragma unroll
        for (int nf = 0; nf < 8; ++nf) {
            int row = r0 + wm * 64 + mf * 16 + g;
            int col = n0 + wn * 64 + nf * 8 + tg * 2;
            float b0v = bias[col], b1v = bias[col + 1];
            *reinterpret_cast<__half2*>(&C[(size_t)row * HDIM + col]) =
                __floats2half2_rn(acc[mf][nf][0] + b0v, acc[mf][nf][1] + b1v);
            *reinterpret_cast<__half2*>(&C[(size_t)(row + 8) * HDIM + col]) =
                __floats2half2_rn(acc[mf][nf][2] + b0v, acc[mf][nf][3] + b1v);
        }
    }
}

// ---------------------------------------------------------------------------
// Final GEMM (fp16): out = Q@Wf + KN@Wpfb[batch] + cpf.  grid (1, 512).
// 2 passes of K=512 (8 BK=64 chunks each) into one 128x256 tile.
// ---------------------------------------------------------------------------
__global__ __launch_bounds__(256, 1)
void final_gemm_kernel(float* __restrict__ out) {
    extern __shared__ char sm_raw[];
    const int r0 = blockIdx.y * 128;
    const int batch = r0 >> 12;
    const __half* W1 = g_WpfbT + (size_t)batch * TDIM * HDIM;
    const int tid = threadIdx.x, warp = tid >> 5, lane = tid & 31;
    const int wm = warp >> 2, wn = warp & 3, g = lane >> 2, tg = lane & 3;

    uint32_t smBase = smem_u32(sm_raw);
    float acc[4][8][4];
#pragma unroll
    for (int a = 0; a < 4; ++a)
#pragma unroll
        for (int b2 = 0; b2 < 8; ++b2)
#pragma unroll
            for (int c = 0; c < 4; ++c) acc[a][b2][c] = 0.0f;

    auto issue = [&](int c) {
        int pass = c >> 3, k0 = (c & 7) * 64;
        load_tile(smBase + (uint32_t)(c % NSTG) * STAGE_BYTES,
                  pass ? g_Kh : g_Qh, pass ? W1 : g_WfT, r0, 0, k0, tid);
    };

    issue(0); CP_COMMIT();
    issue(1); CP_COMMIT();

    const int TOT = 16;
    for (int c = 0; c < TOT; ++c) {
        CP_WAIT1();
        __syncthreads();
        if (c + 2 < TOT) { issue(c + 2); CP_COMMIT(); }
        const __half* As = (const __half*)(sm_raw + (size_t)(c % NSTG) * STAGE_BYTES);
        const __half* Ws = As + 128 * LDT;
        compute_chunk(As, Ws, acc, wm, wn, g, tg);
    }

#pragma unroll
    for (int mf = 0; mf < 4; ++mf) {
#pragma unroll
        for (int nf = 0; nf < 8; ++nf) {
            int row = r0 + wm * 64 + mf * 16 + g;
            int col = wn * 64 + nf * 8 + tg * 2;
            float b0v = g_cpf[col], b1v = g_cpf[col + 1];
            *reinterpret_cast<float2*>(&out[(size_t)row * TDIM + col]) =
                make_float2(acc[mf][nf][0] + b0v, acc[mf][nf][1] + b1v);
            *reinterpret_cast<float2*>(&out[(size_t)(row + 8) * TDIM + col]) =
                make_float2(acc[mf][nf][2] + b0v, acc[mf][nf][3] + b1v);
        }
    }
}

// ---------------------------------------------------------------------------
extern "C" void kernel_launch(void* const* d_in, const int* in_sizes, int n_in,
                              void* d_out, int out_size) {
    const float* x  = (const float*)d_in[0];
    const float* Wq = (const float*)d_in[1];
    const float* bq = (const float*)d_in[2];
    const float* Wk = (const float*)d_in[3];
    const float* bk = (const float*)d_in[4];
    const float* wg = (const float*)d_in[5];
    const float* Wp = (const float*)d_in[6];
    const float* bp = (const float*)d_in[7];
    const float* Wf = (const float*)d_in[8];
    const float* bf = (const float*)d_in[9];
    float* out = (float*)d_out;

    cudaFuncSetAttribute(qk_gemm_kernel, cudaFuncAttributeMaxDynamicSharedMemorySize, SMEM_DYN);
    cudaFuncSetAttribute(final_gemm_kernel, cudaFuncAttributeMaxDynamicSharedMemorySize, SMEM_DYN);

    __half* pWqT; cudaGetSymbolAddress((void**)&pWqT, g_WqT);
    __half* pWkT; cudaGetSymbolAddress((void**)&pWkT, g_WkT);
    __half* pWfT; cudaGetSymbolAddress((void**)&pWfT, g_WfT);

    zero_stats_kernel<<<32, 256>>>();
    conv_x_kernel<<<2048, 256>>>(x);
    transpose_h_kernel<<<dim3(16, 16), dim3(32, 8)>>>(Wq, pWqT, 512, 512);
    transpose_h_kernel<<<dim3(16, 16), dim3(32, 8)>>>(Wk, pWkT, 512, 512);
    transpose_h_kernel<<<dim3(8, 16), dim3(32, 8)>>>(Wf, pWfT, 512, 256);
    prep_kernel<<<33, 256>>>(Wp, Wf, bp, bf);

    qk_gemm_kernel<<<dim3(4, 512), 256, SMEM_DYN>>>(bq, bk);

    rowwise_kernel<<<512, 256>>>(wg);
    finalize_g_kernel<<<16, 512>>>();
    build_wpfbt_kernel<<<dim3(256, 16), 512>>>();

    final_gemm_kernel<<<dim3(1, 512), 256, SMEM_DYN>>>(out);
}

// round 9
// speedup vs baseline: 1.8654x; 1.0339x over previous
#include <cuda_runtime.h>
#include <cuda_fp16.h>
#include <cstdint>

// ---------------------------------------------------------------------------
// EfficientAdditiveAttention — round 9: fp16 mma.m16n8k16 + ldmatrix.x4
// fragment feeds (4x fewer smem instructions), BK=64, single-barrier
// 3-stage cp.async mainloop, 64x64 warp tiles.
//
//   q = x@Wq + bq ; k = x@Wk + bk
//   qw = (q/||q||).w_g ; kn = k/||k||
//   S_b = sum qw^2 ; Gacc_b = sum qw*q ; G_b = SCALE*Gacc/max(SCALE*sqrt(S),EPS)
//   out = q@Wf + kn@(diag(G_b)·Wp@Wf) + (bp@Wf + bf)
// ---------------------------------------------------------------------------

#define BATCH   16
#define SEQ     4096
#define HDIM    512
#define TDIM    256
#define MTOT    (BATCH * SEQ)
#define EPS_F   1e-12f
#define SCALE_F 0.044194173824159216f

// ---------------- scratch (device globals; no runtime alloc) ---------------
__device__ __align__(16) __half g_Xh[(size_t)MTOT * HDIM];     // x in fp16
__device__ __align__(16) __half g_Qh[(size_t)MTOT * HDIM];     // q fp16
__device__ __align__(16) __half g_Kh[(size_t)MTOT * HDIM];     // k -> kn fp16
__device__ __align__(16) __half g_WqT[HDIM * HDIM];            // Wq^T [n][k]
__device__ __align__(16) __half g_WkT[HDIM * HDIM];
__device__ __align__(16) __half g_WfT[TDIM * HDIM];            // Wf^T [256][512]
__device__ __align__(16) __half g_WpfbT[(size_t)BATCH * TDIM * HDIM]; // (diag(G)Wpf)^T
__device__ float g_Wpf[HDIM * TDIM];                           // Wp@Wf fp32
__device__ float g_cpf[TDIM];
__device__ float g_Gacc[BATCH * HDIM];
__device__ float g_S[BATCH];
__device__ float g_G[BATCH * HDIM];

// ---------------------------- helpers --------------------------------------
__device__ __forceinline__ uint32_t smem_u32(const void* p) {
    uint32_t a;
    asm("{ .reg .u64 t; cvta.to.shared.u64 t, %1; cvt.u32.u64 %0, t; }" : "=r"(a) : "l"(p));
    return a;
}

#define CP_ASYNC16(dst, src) \
    asm volatile("cp.async.cg.shared.global [%0], [%1], 16;" :: "r"(dst), "l"(src) : "memory")
#define CP_COMMIT() asm volatile("cp.async.commit_group;" ::: "memory")
#define CP_WAIT1()  asm volatile("cp.async.wait_group 1;" ::: "memory")

__device__ __forceinline__ void mma_f16(float c[4], const uint32_t a[4], const uint32_t b[2]) {
    asm volatile(
        "mma.sync.aligned.m16n8k16.row.col.f32.f16.f16.f32 "
        "{%0,%1,%2,%3}, {%4,%5,%6,%7}, {%8,%9}, {%0,%1,%2,%3};\n"
        : "+f"(c[0]), "+f"(c[1]), "+f"(c[2]), "+f"(c[3])
        : "r"(a[0]), "r"(a[1]), "r"(a[2]), "r"(a[3]), "r"(b[0]), "r"(b[1]));
}

__device__ __forceinline__ void ldsm4(uint32_t& r0, uint32_t& r1, uint32_t& r2, uint32_t& r3,
                                      uint32_t addr) {
    asm volatile("ldmatrix.sync.aligned.m8n8.x4.shared.b16 {%0,%1,%2,%3}, [%4];"
                 : "=r"(r0), "=r"(r1), "=r"(r2), "=r"(r3) : "r"(addr));
}

// stage geometry (halves): BK=64. A tile 128x64 ld=72; W tile 256x64 ld=72.
// LDSM phase: 8 rows x 16B at 144B stride -> banks 4r..4r+3, conflict-free.
#define LDT 72
#define A_BYTES (128 * LDT * 2)                 // 18432
#define W_BYTES (256 * LDT * 2)                 // 36864
#define STAGE_BYTES (A_BYTES + W_BYTES)         // 55296
#define NSTG 3
#define SMEM_DYN (NSTG * STAGE_BYTES)           // 165888

// load one (A 128x64, W 256x64) chunk of halves into a stage
__device__ __forceinline__ void load_tile(uint32_t stA, const __half* __restrict__ A,
                                          const __half* __restrict__ Wt,
                                          int r0, int n0, int k0, int tid) {
    uint32_t stW = stA + A_BYTES;
#pragma unroll
    for (int it = 0; it < 4; ++it) {            // A: 128 rows x 8 chunks = 1024
        int u = tid + it * 256;
        int row = u >> 3, c = u & 7;
        CP_ASYNC16(stA + (uint32_t)(row * LDT * 2 + c * 16),
                   A + (size_t)(r0 + row) * HDIM + k0 + c * 8);
    }
#pragma unroll
    for (int it = 0; it < 8; ++it) {            // W: 256 rows x 8 chunks = 2048
        int u = tid + it * 256;
        int row = u >> 3, c = u & 7;
        CP_ASYNC16(stW + (uint32_t)(row * LDT * 2 + c * 16),
                   Wt + (size_t)(n0 + row) * HDIM + k0 + c * 8);
    }
}

// one BK=64 chunk: 4 k16 steps, warp tile 64x64, ldmatrix.x4 feeds
// aBase: lane-resolved A address for (row wm*64+(l&15), colhalf (l>>4)*8)
// bBase: lane-resolved B address for (row wn*64+(l>>4)*8+(l&7), colhalf ((l>>3)&1)*8)
__device__ __forceinline__ void compute_chunk(uint32_t aBase, uint32_t bBase,
                                              float acc[4][8][4]) {
#pragma unroll
    for (int ks = 0; ks < 4; ++ks) {
        uint32_t af[4][4], bw[8][2];
#pragma unroll
        for (int mf = 0; mf < 4; ++mf)
            ldsm4(af[mf][0], af[mf][1], af[mf][2], af[mf][3],
                  aBase + (uint32_t)((mf * 16 * LDT + ks * 16) * 2));
#pragma unroll
        for (int np = 0; np < 4; ++np)
            ldsm4(bw[2 * np][0], bw[2 * np][1], bw[2 * np + 1][0], bw[2 * np + 1][1],
                  bBase + (uint32_t)((np * 16 * LDT + ks * 16) * 2));
#pragma unroll
        for (int mf = 0; mf < 4; ++mf)
#pragma unroll
            for (int nf = 0; nf < 8; ++nf) mma_f16(acc[mf][nf], af[mf], bw[nf]);
    }
}

// ---------------------------------------------------------------------------
// small kernels
// ---------------------------------------------------------------------------
__global__ void conv_x_kernel(const float* __restrict__ x) {
    size_t gtid = blockIdx.x * blockDim.x + threadIdx.x;
    if (gtid < BATCH * HDIM) g_Gacc[gtid] = 0.0f;      // fold stats zeroing here
    if (gtid < BATCH) g_S[gtid] = 0.0f;
    size_t n4 = (size_t)MTOT * HDIM / 4;
    __half2* dst = reinterpret_cast<__half2*>(g_Xh);
    for (size_t i = gtid; i < n4; i += (size_t)gridDim.x * blockDim.x) {
        float4 v = reinterpret_cast<const float4*>(x)[i];
        dst[2 * i]     = __floats2half2_rn(v.x, v.y);
        dst[2 * i + 1] = __floats2half2_rn(v.z, v.w);
    }
}

// dst[n][k] = half(src[k][n]); src rows=K, cols=N (n contiguous)
__global__ void transpose_h_kernel(const float* __restrict__ src, __half* __restrict__ dst,
                                   int rows, int cols) {
    __shared__ float t[32][33];
    int x0 = blockIdx.x * 32, y0 = blockIdx.y * 32;
    int tx = threadIdx.x, ty = threadIdx.y;
#pragma unroll
    for (int i = 0; i < 4; ++i)
        t[ty + 8 * i][tx] = src[(size_t)(y0 + ty + 8 * i) * cols + x0 + tx];
    __syncthreads();
#pragma unroll
    for (int i = 0; i < 4; ++i)
        dst[(size_t)(x0 + ty + 8 * i) * rows + y0 + tx] = __float2half_rn(t[tx][ty + 8 * i]);
}

__global__ void prep_kernel(const float* __restrict__ Wp, const float* __restrict__ Wf,
                            const float* __restrict__ bp, const float* __restrict__ bf) {
    int j = threadIdx.x;
    if (blockIdx.x < 32) {
        __shared__ float Wp_s[16][512];
        int i0 = blockIdx.x * 16;
        for (int i = threadIdx.x; i < 16 * 512; i += 256)
            Wp_s[i >> 9][i & 511] = Wp[(size_t)(i0 + (i >> 9)) * 512 + (i & 511)];
        __syncthreads();
        float acc[16];
#pragma unroll
        for (int i = 0; i < 16; ++i) acc[i] = 0.0f;
        for (int k = 0; k < 512; ++k) {
            float wf = Wf[(size_t)k * TDIM + j];
#pragma unroll
            for (int i = 0; i < 16; ++i) acc[i] += Wp_s[i][k] * wf;
        }
#pragma unroll
        for (int i = 0; i < 16; ++i) g_Wpf[(size_t)(i0 + i) * TDIM + j] = acc[i];
    } else {
        __shared__ float bp_s[512];
        for (int i = threadIdx.x; i < 512; i += 256) bp_s[i] = bp[i];
        __syncthreads();
        float a = bf[j];
        for (int k = 0; k < 512; ++k) a += bp_s[k] * Wf[(size_t)k * TDIM + j];
        g_cpf[j] = a;
    }
}

__global__ void finalize_g_kernel() {
    int b = blockIdx.x, j = threadIdx.x;
    float denom = fmaxf(SCALE_F * sqrtf(g_S[b]), EPS_F);
    g_G[b * HDIM + j] = SCALE_F * g_Gacc[b * HDIM + j] / denom;
}

// WpfbT[b][n][k] = half(G[b][k] * Wpf[k][n])   grid(256,16) block 512
__global__ void build_wpfbt_kernel() {
    int n = blockIdx.x, b = blockIdx.y, k = threadIdx.x;
    g_WpfbT[((size_t)b * TDIM + n) * HDIM + k] =
        __float2half_rn(g_G[b * HDIM + k] * g_Wpf[(size_t)k * TDIM + n]);
}

// ---------------------------------------------------------------------------
// rowwise: norms + qw + kn(in place, half) + per-batch reductions (half I/O)
// ---------------------------------------------------------------------------
__global__ void rowwise_kernel(const float* __restrict__ wg) {
    __shared__ float wg_s[512];
    __shared__ float Gs[8][512];
    __shared__ float Sq[8];
    const int tid = threadIdx.x, warp = tid >> 5, lane = tid & 31;
    const int r0 = blockIdx.x * 128;
    const int b = r0 >> 12;

    for (int i = tid; i < 512; i += 256) wg_s[i] = wg[i];
    for (int i = tid; i < 8 * 512; i += 256) (&Gs[0][0])[i] = 0.0f;
    __syncthreads();

    float qw2 = 0.0f;
    for (int rt = 0; rt < 16; ++rt) {
        int r = r0 + rt * 8 + warp;
        const __half2* qr = reinterpret_cast<const __half2*>(g_Qh + (size_t)r * HDIM);
        __half2* kr = reinterpret_cast<__half2*>(g_Kh + (size_t)r * HDIM);
        float2 q[8], k[8];
        float sq = 0.0f, sg = 0.0f, sk = 0.0f;
#pragma unroll
        for (int t = 0; t < 8; ++t) {
            int j2 = lane + 32 * t;
            q[t] = __half22float2(qr[j2]);
            k[t] = __half22float2(kr[j2]);
            sq += q[t].x * q[t].x + q[t].y * q[t].y;
            sk += k[t].x * k[t].x + k[t].y * k[t].y;
            sg += q[t].x * wg_s[2 * j2] + q[t].y * wg_s[2 * j2 + 1];
        }
#pragma unroll
        for (int o = 16; o; o >>= 1) {
            sq += __shfl_xor_sync(0xffffffffu, sq, o);
            sg += __shfl_xor_sync(0xffffffffu, sg, o);
            sk += __shfl_xor_sync(0xffffffffu, sk, o);
        }
        float dq = fmaxf(sqrtf(sq), EPS_F);
        float dk = fmaxf(sqrtf(sk), EPS_F);
        float qw = sg / dq;
        float rk = 1.0f / dk;
        qw2 += qw * qw;
#pragma unroll
        for (int t = 0; t < 8; ++t) {
            int j2 = lane + 32 * t;
            kr[j2] = __floats2half2_rn(k[t].x * rk, k[t].y * rk);
            Gs[warp][2 * j2]     += qw * q[t].x;
            Gs[warp][2 * j2 + 1] += qw * q[t].y;
        }
    }
    if (lane == 0) Sq[warp] = qw2;
    __syncthreads();

    for (int j = tid; j < 512; j += 256) {
        float s = 0.0f;
#pragma unroll
        for (int w = 0; w < 8; ++w) s += Gs[w][j];
        atomicAdd(&g_Gacc[b * HDIM + j], s);
    }
    if (tid == 0) {
        float s = 0.0f;
#pragma unroll
        for (int w = 0; w < 8; ++w) s += Sq[w];
        atomicAdd(&g_S[b], s);
    }
}

// ---------------------------------------------------------------------------
// Fused Q/K GEMM (fp16): grid (4, 512). bx<2 -> Q (n0=bx*256), else K.
// CTA 128x256, warp 64x64, BK=64, 3-stage cp.async, ldmatrix feeds.
// ---------------------------------------------------------------------------
__global__ __launch_bounds__(256, 1)
void qk_gemm_kernel(const float* __restrict__ bq, const float* __restrict__ bk) {
    extern __shared__ char sm_raw[];
    const int bx = blockIdx.x;
    const bool isQ = (bx < 2);
    const __half* Wt = isQ ? g_WqT : g_WkT;
    const float* bias = isQ ? bq : bk;
    __half* C = isQ ? g_Qh : g_Kh;
    const int n0 = (bx & 1) * 256;
    const int r0 = blockIdx.y * 128;
    const int tid = threadIdx.x, warp = tid >> 5, lane = tid & 31;
    const int wm = warp >> 2, wn = warp & 3, g = lane >> 2, tg = lane & 3;

    uint32_t smBase = smem_u32(sm_raw);
    // lane-resolved ldmatrix base offsets (within a stage)
    const uint32_t aOff = (uint32_t)(((wm * 64 + (lane & 15)) * LDT + ((lane >> 4) * 8)) * 2);
    const uint32_t bOff = (uint32_t)(A_BYTES +
        ((wn * 64 + ((lane >> 4) * 8) + (lane & 7)) * LDT + (((lane >> 3) & 1) * 8)) * 2);

    float acc[4][8][4];
#pragma unroll
    for (int a = 0; a < 4; ++a)
#pragma unroll
        for (int b2 = 0; b2 < 8; ++b2)
#pragma unroll
            for (int c = 0; c < 4; ++c) acc[a][b2][c] = 0.0f;

    load_tile(smBase + 0 * STAGE_BYTES, g_Xh, Wt, r0, n0, 0, tid);  CP_COMMIT();
    load_tile(smBase + 1 * STAGE_BYTES, g_Xh, Wt, r0, n0, 64, tid); CP_COMMIT();

    const int TOT = 8;                                   // K=512 / BK=64
    for (int c = 0; c < TOT; ++c) {
        CP_WAIT1();                                      // chunk c resident
        __syncthreads();                                 // all warps done with c-1
        if (c + 2 < TOT) {
            load_tile(smBase + (uint32_t)((c + 2) % NSTG) * STAGE_BYTES, g_Xh, Wt,
                      r0, n0, (c + 2) * 64, tid);
            CP_COMMIT();
        }
        uint32_t stage = smBase + (uint32_t)(c % NSTG) * STAGE_BYTES;
        compute_chunk(stage + aOff, stage + bOff, acc);
    }

#pragma unroll
    for (int mf = 0; mf < 4; ++mf) {
#pragma unroll
        for (int nf = 0; nf < 8; ++nf) {
            int row = r0 + wm * 64 + mf * 16 + g;
            int col = n0 + wn * 64 + nf * 8 + tg * 2;
            float b0v = bias[col], b1v = bias[col + 1];
            *reinterpret_cast<__half2*>(&C[(size_t)row * HDIM + col]) =
                __floats2half2_rn(acc[mf][nf][0] + b0v, acc[mf][nf][1] + b1v);
            *reinterpret_cast<__half2*>(&C[(size_t)(row + 8) * HDIM + col]) =
                __floats2half2_rn(acc[mf][nf][2] + b0v, acc[mf][nf][3] + b1v);
        }
    }
}

// ---------------------------------------------------------------------------
// Final GEMM (fp16): out = Q@Wf + KN@Wpfb[batch] + cpf.  grid (1, 512).
// 2 passes of K=512 (8 BK=64 chunks each) into one 128x256 tile.
// ---------------------------------------------------------------------------
__global__ __launch_bounds__(256, 1)
void final_gemm_kernel(float* __restrict__ out) {
    extern __shared__ char sm_raw[];
    const int r0 = blockIdx.y * 128;
    const int batch = r0 >> 12;
    const __half* W1 = g_WpfbT + (size_t)batch * TDIM * HDIM;
    const int tid = threadIdx.x, warp = tid >> 5, lane = tid & 31;
    const int wm = warp >> 2, wn = warp & 3, g = lane >> 2, tg = lane & 3;

    uint32_t smBase = smem_u32(sm_raw);
    const uint32_t aOff = (uint32_t)(((wm * 64 + (lane & 15)) * LDT + ((lane >> 4) * 8)) * 2);
    const uint32_t bOff = (uint32_t)(A_BYTES +
        ((wn * 64 + ((lane >> 4) * 8) + (lane & 7)) * LDT + (((lane >> 3) & 1) * 8)) * 2);

    float acc[4][8][4];
#pragma unroll
    for (int a = 0; a < 4; ++a)
#pragma unroll
        for (int b2 = 0; b2 < 8; ++b2)
#pragma unroll
            for (int c = 0; c < 4; ++c) acc[a][b2][c] = 0.0f;

    auto issue = [&](int c) {
        int pass = c >> 3, k0 = (c & 7) * 64;
        load_tile(smBase + (uint32_t)(c % NSTG) * STAGE_BYTES,
                  pass ? g_Kh : g_Qh, pass ? W1 : g_WfT, r0, 0, k0, tid);
    };

    issue(0); CP_COMMIT();
    issue(1); CP_COMMIT();

    const int TOT = 16;
    for (int c = 0; c < TOT; ++c) {
        CP_WAIT1();
        __syncthreads();
        if (c + 2 < TOT) { issue(c + 2); CP_COMMIT(); }
        uint32_t stage = smBase + (uint32_t)(c % NSTG) * STAGE_BYTES;
        compute_chunk(stage + aOff, stage + bOff, acc);
    }

#pragma unroll
    for (int mf = 0; mf < 4; ++mf) {
#pragma unroll
        for (int nf = 0; nf < 8; ++nf) {
            int row = r0 + wm * 64 + mf * 16 + g;
            int col = wn * 64 + nf * 8 + tg * 2;
            float b0v = g_cpf[col], b1v = g_cpf[col + 1];
            *reinterpret_cast<float2*>(&out[(size_t)row * TDIM + col]) =
                make_float2(acc[mf][nf][0] + b0v, acc[mf][nf][1] + b1v);
            *reinterpret_cast<float2*>(&out[(size_t)(row + 8) * TDIM + col]) =
                make_float2(acc[mf][nf][2] + b0v, acc[mf][nf][3] + b1v);
        }
    }
}

// ---------------------------------------------------------------------------
extern "C" void kernel_launch(void* const* d_in, const int* in_sizes, int n_in,
                              void* d_out, int out_size) {
    const float* x  = (const float*)d_in[0];
    const float* Wq = (const float*)d_in[1];
    const float* bq = (const float*)d_in[2];
    const float* Wk = (const float*)d_in[3];
    const float* bk = (const float*)d_in[4];
    const float* wg = (const float*)d_in[5];
    const float* Wp = (const float*)d_in[6];
    const float* bp = (const float*)d_in[7];
    const float* Wf = (const float*)d_in[8];
    const float* bf = (const float*)d_in[9];
    float* out = (float*)d_out;

    cudaFuncSetAttribute(qk_gemm_kernel, cudaFuncAttributeMaxDynamicSharedMemorySize, SMEM_DYN);
    cudaFuncSetAttribute(final_gemm_kernel, cudaFuncAttributeMaxDynamicSharedMemorySize, SMEM_DYN);

    __half* pWqT; cudaGetSymbolAddress((void**)&pWqT, g_WqT);
    __half* pWkT; cudaGetSymbolAddress((void**)&pWkT, g_WkT);
    __half* pWfT; cudaGetSymbolAddress((void**)&pWfT, g_WfT);

    conv_x_kernel<<<2048, 256>>>(x);                                   // 1 (+ stats zero)
    transpose_h_kernel<<<dim3(16, 16), dim3(32, 8)>>>(Wq, pWqT, 512, 512);  // 2
    transpose_h_kernel<<<dim3(16, 16), dim3(32, 8)>>>(Wk, pWkT, 512, 512);  // 3
    transpose_h_kernel<<<dim3(8, 16), dim3(32, 8)>>>(Wf, pWfT, 512, 256);   // 4
    prep_kernel<<<33, 256>>>(Wp, Wf, bp, bf);                               // 5
    qk_gemm_kernel<<<dim3(4, 512), 256, SMEM_DYN>>>(bq, bk);                // 6 <- ncu slot
    rowwise_kernel<<<512, 256>>>(wg);
    finalize_g_kernel<<<16, 512>>>();
    build_wpfbt_kernel<<<dim3(256, 16), 512>>>();
    final_gemm_kernel<<<dim3(1, 512), 256, SMEM_DYN>>>(out);
}

// round 10
// speedup vs baseline: 2.0050x; 1.0749x over previous
#include <cuda_runtime.h>
#include <cuda_fp16.h>
#include <cstdint>

// ---------------------------------------------------------------------------
// EfficientAdditiveAttention — round 10: 2 CTAs/SM. CTA tile 128x128,
// warp tile 64x32 (acc 64 regs), 3-stage cp.async (36KB/stage),
// ldmatrix.x4 feeds, fp16 mma.m16n8k16.
//
//   q = x@Wq + bq ; k = x@Wk + bk
//   qw = (q/||q||).w_g ; kn = k/||k||
//   S_b = sum qw^2 ; Gacc_b = sum qw*q ; G_b = SCALE*Gacc/max(SCALE*sqrt(S),EPS)
//   out = q@Wf + kn@(diag(G_b)·Wp@Wf) + (bp@Wf + bf)
// ---------------------------------------------------------------------------

#define BATCH   16
#define SEQ     4096
#define HDIM    512
#define TDIM    256
#define MTOT    (BATCH * SEQ)
#define EPS_F   1e-12f
#define SCALE_F 0.044194173824159216f

// ---------------- scratch (device globals; no runtime alloc) ---------------
__device__ __align__(16) __half g_Xh[(size_t)MTOT * HDIM];     // x in fp16
__device__ __align__(16) __half g_Qh[(size_t)MTOT * HDIM];     // q fp16
__device__ __align__(16) __half g_Kh[(size_t)MTOT * HDIM];     // k -> kn fp16
__device__ __align__(16) __half g_WqT[HDIM * HDIM];            // Wq^T [n][k]
__device__ __align__(16) __half g_WkT[HDIM * HDIM];
__device__ __align__(16) __half g_WfT[TDIM * HDIM];            // Wf^T [256][512]
__device__ __align__(16) __half g_WpfbT[(size_t)BATCH * TDIM * HDIM]; // (diag(G)Wpf)^T
__device__ float g_Wpf[HDIM * TDIM];                           // Wp@Wf fp32
__device__ float g_cpf[TDIM];
__device__ float g_Gacc[BATCH * HDIM];
__device__ float g_S[BATCH];
__device__ float g_G[BATCH * HDIM];

// ---------------------------- helpers --------------------------------------
__device__ __forceinline__ uint32_t smem_u32(const void* p) {
    uint32_t a;
    asm("{ .reg .u64 t; cvta.to.shared.u64 t, %1; cvt.u32.u64 %0, t; }" : "=r"(a) : "l"(p));
    return a;
}

#define CP_ASYNC16(dst, src) \
    asm volatile("cp.async.cg.shared.global [%0], [%1], 16;" :: "r"(dst), "l"(src) : "memory")
#define CP_COMMIT() asm volatile("cp.async.commit_group;" ::: "memory")
#define CP_WAIT1()  asm volatile("cp.async.wait_group 1;" ::: "memory")

__device__ __forceinline__ void mma_f16(float c[4], const uint32_t a[4], const uint32_t b[2]) {
    asm volatile(
        "mma.sync.aligned.m16n8k16.row.col.f32.f16.f16.f32 "
        "{%0,%1,%2,%3}, {%4,%5,%6,%7}, {%8,%9}, {%0,%1,%2,%3};\n"
        : "+f"(c[0]), "+f"(c[1]), "+f"(c[2]), "+f"(c[3])
        : "r"(a[0]), "r"(a[1]), "r"(a[2]), "r"(a[3]), "r"(b[0]), "r"(b[1]));
}

__device__ __forceinline__ void ldsm4(uint32_t& r0, uint32_t& r1, uint32_t& r2, uint32_t& r3,
                                      uint32_t addr) {
    asm volatile("ldmatrix.sync.aligned.m8n8.x4.shared.b16 {%0,%1,%2,%3}, [%4];"
                 : "=r"(r0), "=r"(r1), "=r"(r2), "=r"(r3) : "r"(addr));
}

// stage geometry: BK=64. A tile 128x64 ld=72; W tile 128x64 ld=72.
#define LDT 72
#define A_BYTES (128 * LDT * 2)                 // 18432
#define W_BYTES (128 * LDT * 2)                 // 18432
#define STAGE_BYTES (A_BYTES + W_BYTES)         // 36864
#define NSTG 3
#define SMEM_DYN (NSTG * STAGE_BYTES)           // 110592 -> 2 CTAs/SM

// load one (A 128x64, W 128x64) chunk of halves into a stage
__device__ __forceinline__ void load_tile(uint32_t stA, const __half* __restrict__ A,
                                          const __half* __restrict__ Wt,
                                          int r0, int n0, int k0, int tid) {
    uint32_t stW = stA + A_BYTES;
#pragma unroll
    for (int it = 0; it < 4; ++it) {            // A: 128 rows x 8 granules = 1024
        int u = tid + it * 256;
        int row = u >> 3, c = u & 7;
        CP_ASYNC16(stA + (uint32_t)(row * LDT * 2 + c * 16),
                   A + (size_t)(r0 + row) * HDIM + k0 + c * 8);
    }
#pragma unroll
    for (int it = 0; it < 4; ++it) {            // W: 128 rows x 8 granules = 1024
        int u = tid + it * 256;
        int row = u >> 3, c = u & 7;
        CP_ASYNC16(stW + (uint32_t)(row * LDT * 2 + c * 16),
                   Wt + (size_t)(n0 + row) * HDIM + k0 + c * 8);
    }
}

// one BK=64 chunk: 4 k16 steps, warp tile 64x32, ldmatrix.x4 feeds
__device__ __forceinline__ void compute_chunk(uint32_t aBase, uint32_t bBase,
                                              float acc[4][4][4]) {
#pragma unroll
    for (int ks = 0; ks < 4; ++ks) {
        uint32_t af[4][4], bw[4][2];
#pragma unroll
        for (int mf = 0; mf < 4; ++mf)
            ldsm4(af[mf][0], af[mf][1], af[mf][2], af[mf][3],
                  aBase + (uint32_t)((mf * 16 * LDT + ks * 16) * 2));
#pragma unroll
        for (int np = 0; np < 2; ++np)
            ldsm4(bw[2 * np][0], bw[2 * np][1], bw[2 * np + 1][0], bw[2 * np + 1][1],
                  bBase + (uint32_t)((np * 16 * LDT + ks * 16) * 2));
#pragma unroll
        for (int mf = 0; mf < 4; ++mf)
#pragma unroll
            for (int nf = 0; nf < 4; ++nf) mma_f16(acc[mf][nf], af[mf], bw[nf]);
    }
}

// ---------------------------------------------------------------------------
// small kernels
// ---------------------------------------------------------------------------
__global__ void conv_x_kernel(const float* __restrict__ x) {
    size_t gtid = blockIdx.x * blockDim.x + threadIdx.x;
    if (gtid < BATCH * HDIM) g_Gacc[gtid] = 0.0f;      // fold stats zeroing here
    if (gtid < BATCH) g_S[gtid] = 0.0f;
    size_t n4 = (size_t)MTOT * HDIM / 4;
    __half2* dst = reinterpret_cast<__half2*>(g_Xh);
    for (size_t i = gtid; i < n4; i += (size_t)gridDim.x * blockDim.x) {
        float4 v = reinterpret_cast<const float4*>(x)[i];
        dst[2 * i]     = __floats2half2_rn(v.x, v.y);
        dst[2 * i + 1] = __floats2half2_rn(v.z, v.w);
    }
}

// dst[n][k] = half(src[k][n]); src rows=K, cols=N (n contiguous)
__global__ void transpose_h_kernel(const float* __restrict__ src, __half* __restrict__ dst,
                                   int rows, int cols) {
    __shared__ float t[32][33];
    int x0 = blockIdx.x * 32, y0 = blockIdx.y * 32;
    int tx = threadIdx.x, ty = threadIdx.y;
#pragma unroll
    for (int i = 0; i < 4; ++i)
        t[ty + 8 * i][tx] = src[(size_t)(y0 + ty + 8 * i) * cols + x0 + tx];
    __syncthreads();
#pragma unroll
    for (int i = 0; i < 4; ++i)
        dst[(size_t)(x0 + ty + 8 * i) * rows + y0 + tx] = __float2half_rn(t[tx][ty + 8 * i]);
}

__global__ void prep_kernel(const float* __restrict__ Wp, const float* __restrict__ Wf,
                            const float* __restrict__ bp, const float* __restrict__ bf) {
    int j = threadIdx.x;
    if (blockIdx.x < 32) {
        __shared__ float Wp_s[16][512];
        int i0 = blockIdx.x * 16;
        for (int i = threadIdx.x; i < 16 * 512; i += 256)
            Wp_s[i >> 9][i & 511] = Wp[(size_t)(i0 + (i >> 9)) * 512 + (i & 511)];
        __syncthreads();
        float acc[16];
#pragma unroll
        for (int i = 0; i < 16; ++i) acc[i] = 0.0f;
        for (int k = 0; k < 512; ++k) {
            float wf = Wf[(size_t)k * TDIM + j];
#pragma unroll
            for (int i = 0; i < 16; ++i) acc[i] += Wp_s[i][k] * wf;
        }
#pragma unroll
        for (int i = 0; i < 16; ++i) g_Wpf[(size_t)(i0 + i) * TDIM + j] = acc[i];
    } else {
        __shared__ float bp_s[512];
        for (int i = threadIdx.x; i < 512; i += 256) bp_s[i] = bp[i];
        __syncthreads();
        float a = bf[j];
        for (int k = 0; k < 512; ++k) a += bp_s[k] * Wf[(size_t)k * TDIM + j];
        g_cpf[j] = a;
    }
}

__global__ void finalize_g_kernel() {
    int b = blockIdx.x, j = threadIdx.x;
    float denom = fmaxf(SCALE_F * sqrtf(g_S[b]), EPS_F);
    g_G[b * HDIM + j] = SCALE_F * g_Gacc[b * HDIM + j] / denom;
}

// WpfbT[b][n][k] = half(G[b][k] * Wpf[k][n])   grid(256,16) block 512
__global__ void build_wpfbt_kernel() {
    int n = blockIdx.x, b = blockIdx.y, k = threadIdx.x;
    g_WpfbT[((size_t)b * TDIM + n) * HDIM + k] =
        __float2half_rn(g_G[b * HDIM + k] * g_Wpf[(size_t)k * TDIM + n]);
}

// ---------------------------------------------------------------------------
// rowwise: norms + qw + kn(in place, half) + per-batch reductions (half I/O)
// ---------------------------------------------------------------------------
__global__ void rowwise_kernel(const float* __restrict__ wg) {
    __shared__ float wg_s[512];
    __shared__ float Gs[8][512];
    __shared__ float Sq[8];
    const int tid = threadIdx.x, warp = tid >> 5, lane = tid & 31;
    const int r0 = blockIdx.x * 128;
    const int b = r0 >> 12;

    for (int i = tid; i < 512; i += 256) wg_s[i] = wg[i];
    for (int i = tid; i < 8 * 512; i += 256) (&Gs[0][0])[i] = 0.0f;
    __syncthreads();

    float qw2 = 0.0f;
    for (int rt = 0; rt < 16; ++rt) {
        int r = r0 + rt * 8 + warp;
        const __half2* qr = reinterpret_cast<const __half2*>(g_Qh + (size_t)r * HDIM);
        __half2* kr = reinterpret_cast<__half2*>(g_Kh + (size_t)r * HDIM);
        float2 q[8], k[8];
        float sq = 0.0f, sg = 0.0f, sk = 0.0f;
#pragma unroll
        for (int t = 0; t < 8; ++t) {
            int j2 = lane + 32 * t;
            q[t] = __half22float2(qr[j2]);
            k[t] = __half22float2(kr[j2]);
            sq += q[t].x * q[t].x + q[t].y * q[t].y;
            sk += k[t].x * k[t].x + k[t].y * k[t].y;
            sg += q[t].x * wg_s[2 * j2] + q[t].y * wg_s[2 * j2 + 1];
        }
#pragma unroll
        for (int o = 16; o; o >>= 1) {
            sq += __shfl_xor_sync(0xffffffffu, sq, o);
            sg += __shfl_xor_sync(0xffffffffu, sg, o);
            sk += __shfl_xor_sync(0xffffffffu, sk, o);
        }
        float dq = fmaxf(sqrtf(sq), EPS_F);
        float dk = fmaxf(sqrtf(sk), EPS_F);
        float qw = sg / dq;
        float rk = 1.0f / dk;
        qw2 += qw * qw;
#pragma unroll
        for (int t = 0; t < 8; ++t) {
            int j2 = lane + 32 * t;
            kr[j2] = __floats2half2_rn(k[t].x * rk, k[t].y * rk);
            Gs[warp][2 * j2]     += qw * q[t].x;
            Gs[warp][2 * j2 + 1] += qw * q[t].y;
        }
    }
    if (lane == 0) Sq[warp] = qw2;
    __syncthreads();

    for (int j = tid; j < 512; j += 256) {
        float s = 0.0f;
#pragma unroll
        for (int w = 0; w < 8; ++w) s += Gs[w][j];
        atomicAdd(&g_Gacc[b * HDIM + j], s);
    }
    if (tid == 0) {
        float s = 0.0f;
#pragma unroll
        for (int w = 0; w < 8; ++w) s += Sq[w];
        atomicAdd(&g_S[b], s);
    }
}

// ---------------------------------------------------------------------------
// Fused Q/K GEMM (fp16): grid (8, 512). bx<4 -> Q (n0=bx*128), else K.
// CTA 128x128, warp 64x32, BK=64, 3-stage cp.async, 2 CTAs/SM.
// ---------------------------------------------------------------------------
__global__ __launch_bounds__(256, 2)
void qk_gemm_kernel(const float* __restrict__ bq, const float* __restrict__ bk) {
    extern __shared__ char sm_raw[];
    const int bx = blockIdx.x;
    const bool isQ = (bx < 4);
    const __half* Wt = isQ ? g_WqT : g_WkT;
    const float* bias = isQ ? bq : bk;
    __half* C = isQ ? g_Qh : g_Kh;
    const int n0 = (bx & 3) * 128;
    const int r0 = blockIdx.y * 128;
    const int tid = threadIdx.x, warp = tid >> 5, lane = tid & 31;
    const int wm = warp >> 2, wn = warp & 3, g = lane >> 2, tg = lane & 3;

    uint32_t smBase = smem_u32(sm_raw);
    const uint32_t aOff = (uint32_t)(((wm * 64 + (lane & 15)) * LDT + ((lane >> 4) * 8)) * 2);
    const uint32_t bOff = (uint32_t)(A_BYTES +
        ((wn * 32 + ((lane >> 4) * 8) + (lane & 7)) * LDT + (((lane >> 3) & 1) * 8)) * 2);

    float acc[4][4][4];
#pragma unroll
    for (int a = 0; a < 4; ++a)
#pragma unroll
        for (int b2 = 0; b2 < 4; ++b2)
#pragma unroll
            for (int c = 0; c < 4; ++c) acc[a][b2][c] = 0.0f;

    load_tile(smBase + 0 * STAGE_BYTES, g_Xh, Wt, r0, n0, 0, tid);  CP_COMMIT();
    load_tile(smBase + 1 * STAGE_BYTES, g_Xh, Wt, r0, n0, 64, tid); CP_COMMIT();

    const int TOT = 8;                                   // K=512 / BK=64
    for (int c = 0; c < TOT; ++c) {
        CP_WAIT1();                                      // chunk c resident
        __syncthreads();                                 // all warps done with c-1
        if (c + 2 < TOT) {
            load_tile(smBase + (uint32_t)((c + 2) % NSTG) * STAGE_BYTES, g_Xh, Wt,
                      r0, n0, (c + 2) * 64, tid);
            CP_COMMIT();
        }
        uint32_t stage = smBase + (uint32_t)(c % NSTG) * STAGE_BYTES;
        compute_chunk(stage + aOff, stage + bOff, acc);
    }

#pragma unroll
    for (int mf = 0; mf < 4; ++mf) {
#pragma unroll
        for (int nf = 0; nf < 4; ++nf) {
            int row = r0 + wm * 64 + mf * 16 + g;
            int col = n0 + wn * 32 + nf * 8 + tg * 2;
            float b0v = bias[col], b1v = bias[col + 1];
            *reinterpret_cast<__half2*>(&C[(size_t)row * HDIM + col]) =
                __floats2half2_rn(acc[mf][nf][0] + b0v, acc[mf][nf][1] + b1v);
            *reinterpret_cast<__half2*>(&C[(size_t)(row + 8) * HDIM + col]) =
                __floats2half2_rn(acc[mf][nf][2] + b0v, acc[mf][nf][3] + b1v);
        }
    }
}

// ---------------------------------------------------------------------------
// Final GEMM (fp16): out = Q@Wf + KN@Wpfb[batch] + cpf.  grid (2, 512).
// 2 passes of K=512 (8 BK=64 chunks each) into one 128x128 tile.
// ---------------------------------------------------------------------------
__global__ __launch_bounds__(256, 2)
void final_gemm_kernel(float* __restrict__ out) {
    extern __shared__ char sm_raw[];
    const int n0 = blockIdx.x * 128;
    const int r0 = blockIdx.y * 128;
    const int batch = r0 >> 12;
    const __half* W1 = g_WpfbT + (size_t)batch * TDIM * HDIM;
    const int tid = threadIdx.x, warp = tid >> 5, lane = tid & 31;
    const int wm = warp >> 2, wn = warp & 3, g = lane >> 2, tg = lane & 3;

    uint32_t smBase = smem_u32(sm_raw);
    const uint32_t aOff = (uint32_t)(((wm * 64 + (lane & 15)) * LDT + ((lane >> 4) * 8)) * 2);
    const uint32_t bOff = (uint32_t)(A_BYTES +
        ((wn * 32 + ((lane >> 4) * 8) + (lane & 7)) * LDT + (((lane >> 3) & 1) * 8)) * 2);

    float acc[4][4][4];
#pragma unroll
    for (int a = 0; a < 4; ++a)
#pragma unroll
        for (int b2 = 0; b2 < 4; ++b2)
#pragma unroll
            for (int c = 0; c < 4; ++c) acc[a][b2][c] = 0.0f;

    auto issue = [&](int c) {
        int pass = c >> 3, k0 = (c & 7) * 64;
        load_tile(smBase + (uint32_t)(c % NSTG) * STAGE_BYTES,
                  pass ? g_Kh : g_Qh, pass ? W1 : g_WfT, r0, n0, k0, tid);
    };

    issue(0); CP_COMMIT();
    issue(1); CP_COMMIT();

    const int TOT = 16;
    for (int c = 0; c < TOT; ++c) {
        CP_WAIT1();
        __syncthreads();
        if (c + 2 < TOT) { issue(c + 2); CP_COMMIT(); }
        uint32_t stage = smBase + (uint32_t)(c % NSTG) * STAGE_BYTES;
        compute_chunk(stage + aOff, stage + bOff, acc);
    }

#pragma unroll
    for (int mf = 0; mf < 4; ++mf) {
#pragma unroll
        for (int nf = 0; nf < 4; ++nf) {
            int row = r0 + wm * 64 + mf * 16 + g;
            int col = n0 + wn * 32 + nf * 8 + tg * 2;
            float b0v = g_cpf[col], b1v = g_cpf[col + 1];
            *reinterpret_cast<float2*>(&out[(size_t)row * TDIM + col]) =
                make_float2(acc[mf][nf][0] + b0v, acc[mf][nf][1] + b1v);
            *reinterpret_cast<float2*>(&out[(size_t)(row + 8) * TDIM + col]) =
                make_float2(acc[mf][nf][2] + b0v, acc[mf][nf][3] + b1v);
        }
    }
}

// ---------------------------------------------------------------------------
extern "C" void kernel_launch(void* const* d_in, const int* in_sizes, int n_in,
                              void* d_out, int out_size) {
    const float* x  = (const float*)d_in[0];
    const float* Wq = (const float*)d_in[1];
    const float* bq = (const float*)d_in[2];
    const float* Wk = (const float*)d_in[3];
    const float* bk = (const float*)d_in[4];
    const float* wg = (const float*)d_in[5];
    const float* Wp = (const float*)d_in[6];
    const float* bp = (const float*)d_in[7];
    const float* Wf = (const float*)d_in[8];
    const float* bf = (const float*)d_in[9];
    float* out = (float*)d_out;

    cudaFuncSetAttribute(qk_gemm_kernel, cudaFuncAttributeMaxDynamicSharedMemorySize, SMEM_DYN);
    cudaFuncSetAttribute(final_gemm_kernel, cudaFuncAttributeMaxDynamicSharedMemorySize, SMEM_DYN);

    __half* pWqT; cudaGetSymbolAddress((void**)&pWqT, g_WqT);
    __half* pWkT; cudaGetSymbolAddress((void**)&pWkT, g_WkT);
    __half* pWfT; cudaGetSymbolAddress((void**)&pWfT, g_WfT);

    conv_x_kernel<<<2048, 256>>>(x);                                   // 1 (+ stats zero)
    transpose_h_kernel<<<dim3(16, 16), dim3(32, 8)>>>(Wq, pWqT, 512, 512);  // 2
    transpose_h_kernel<<<dim3(16, 16), dim3(32, 8)>>>(Wk, pWkT, 512, 512);  // 3
    transpose_h_kernel<<<dim3(8, 16), dim3(32, 8)>>>(Wf, pWfT, 512, 256);   // 4
    prep_kernel<<<33, 256>>>(Wp, Wf, bp, bf);                               // 5
    qk_gemm_kernel<<<dim3(8, 512), 256, SMEM_DYN>>>(bq, bk);                // 6 <- ncu slot
    rowwise_kernel<<<512, 256>>>(wg);
    finalize_g_kernel<<<16, 512>>>();
    build_wpfbt_kernel<<<dim3(256, 16), 512>>>();
    final_gemm_kernel<<<dim3(2, 512), 256, SMEM_DYN>>>(out);
}